// round 9
// baseline (speedup 1.0000x reference)
#include <cuda_runtime.h>
#include <cuda_bf16.h>
#include <cstdint>

#define BB 4
#define NN 2048
#define CC 320
#define HH 5
#define DD 64
#define GG (BB*HH)      // 20
#define ROWS (BB*NN)    // 8192

// scratch (allocation-free rule: __device__ globals)
__device__ __nv_bfloat16 g_qh[GG*NN*DD];   // folded 0.125*e_i, hi
__device__ __nv_bfloat16 g_ql[GG*NN*DD];   // lo
__device__ __nv_bfloat16 g_kh[GG*NN*DD];   // folded e_j, hi
__device__ __nv_bfloat16 g_kl[GG*NN*DD];   // lo
__device__ float         g_v [GG*NN*DD];   // fp32 (pre-transpose)
__device__ __nv_bfloat16 g_vth[GG*DD*NN];  // transposed (g,d,n), hi
__device__ __nv_bfloat16 g_vtl[GG*DD*NN];  // lo
__device__ __nv_bfloat16 g_oh[ROWS*CC];    // attn out, merged (b*N+n, h*64+d), hi
__device__ __nv_bfloat16 g_ol[ROWS*CC];    // lo

// ============================ helpers ======================================
__device__ __forceinline__ void mma_bf16(float* d,
    uint32_t a0, uint32_t a1, uint32_t a2, uint32_t a3,
    uint32_t b0, uint32_t b1)
{
    asm volatile(
        "mma.sync.aligned.m16n8k16.row.col.f32.bf16.bf16.f32 "
        "{%0,%1,%2,%3}, {%4,%5,%6,%7}, {%8,%9}, {%0,%1,%2,%3};"
        : "+f"(d[0]), "+f"(d[1]), "+f"(d[2]), "+f"(d[3])
        : "r"(a0), "r"(a1), "r"(a2), "r"(a3), "r"(b0), "r"(b1));
}

__device__ __forceinline__ void ldm_x4(uint32_t& r0, uint32_t& r1,
                                       uint32_t& r2, uint32_t& r3, uint32_t addr)
{
    asm volatile("ldmatrix.sync.aligned.m8n8.x4.shared.b16 {%0,%1,%2,%3}, [%4];"
        : "=r"(r0), "=r"(r1), "=r"(r2), "=r"(r3) : "r"(addr));
}

__device__ __forceinline__ void bf16_split(float v, __nv_bfloat16& h, __nv_bfloat16& l) {
    h = __float2bfloat16(v);
    l = __float2bfloat16(v - __bfloat162float(h));
}

__device__ __forceinline__ uint32_t pack_bf16(float a, float b) {
    __nv_bfloat162 t = __floats2bfloat162_rn(a, b);
    return *(uint32_t*)&t;
}

__device__ __forceinline__ uint32_t smem_u32(const void* p) {
    uint32_t a;
    asm("{ .reg .u64 t; cvta.to.shared.u64 t, %1; cvt.u32.u64 %0, t; }"
        : "=r"(a) : "l"(p));
    return a;
}

__device__ __forceinline__ void cp16(uint32_t dst, const void* src) {
    asm volatile("cp.async.cg.shared.global [%0], [%1], 16;"
                 :: "r"(dst), "l"(src) : "memory");
}
#define CP_COMMIT() asm volatile("cp.async.commit_group;" ::: "memory")
#define CP_WAIT0()  asm volatile("cp.async.wait_group 0;" ::: "memory")

// ---------------------------------------------------------------------------
// Kernel 1: QKV projection via bf16 hi/lo 3-chain MMA (verified R7).
// ---------------------------------------------------------------------------
#define X_STRIDE_W 20      // words per row (40 halves: 32 data + 8 pad)
__global__ void __launch_bounds__(256)
qkv_mma_kernel(const float* __restrict__ x,
               const float* __restrict__ Wq,
               const float* __restrict__ Wk,
               const float* __restrict__ Wv,
               const float* __restrict__ edge)
{
    __shared__ uint32_t smq[128*X_STRIDE_W*2 + 64*X_STRIDE_W*2];
    uint32_t* XhW = smq;
    uint32_t* XlW = XhW + 128*X_STRIDE_W;
    uint32_t* WhW = XlW + 128*X_STRIDE_W;
    uint32_t* WlW = WhW + 64*X_STRIDE_W;
    __nv_bfloat16* Xh = (__nv_bfloat16*)XhW;
    __nv_bfloat16* Xl = (__nv_bfloat16*)XlW;
    __nv_bfloat16* Wh = (__nv_bfloat16*)WhW;
    __nv_bfloat16* Wl = (__nv_bfloat16*)WlW;

    const int tid  = threadIdx.x;
    const int wid  = tid >> 5;
    const int lane = tid & 31;
    const int lq   = lane >> 2;
    const int cq   = lane & 3;
    const int rb   = wid * 16;
    const int colt = blockIdx.x;       // 0..14
    const int ot   = colt / 5;         // 0=q 1=k 2=v
    const int h    = colt % 5;
    const int wc0  = h * 64;
    const int row0 = blockIdx.y * 128;
    const float* __restrict__ W = (ot == 0) ? Wq : (ot == 1) ? Wk : Wv;

    float acc[8][4] = {};

    for (int k0 = 0; k0 < CC; k0 += 32) {
        __syncthreads();
        #pragma unroll
        for (int i = 0; i < 16; i++) {
            int e = tid + 256*i;
            int kk = e & 31, r = e >> 5;
            float v = x[(row0 + r)*CC + k0 + kk];
            __nv_bfloat16 hh, ll; bf16_split(v, hh, ll);
            Xh[r*40 + kk] = hh;
            Xl[r*40 + kk] = ll;
        }
        #pragma unroll
        for (int i = 0; i < 8; i++) {
            int e = tid + 256*i;
            int n = e & 63, kk = e >> 6;
            float v = W[(k0 + kk)*CC + wc0 + n];
            __nv_bfloat16 hh, ll; bf16_split(v, hh, ll);
            Wh[n*40 + kk] = hh;
            Wl[n*40 + kk] = ll;
        }
        __syncthreads();

        #pragma unroll
        for (int kc = 0; kc < 2; kc++) {
            const int wi = kc*8 + cq;
            uint32_t ah0 = XhW[(rb + lq    )*X_STRIDE_W + wi];
            uint32_t ah1 = XhW[(rb + lq + 8)*X_STRIDE_W + wi];
            uint32_t ah2 = XhW[(rb + lq    )*X_STRIDE_W + wi + 4];
            uint32_t ah3 = XhW[(rb + lq + 8)*X_STRIDE_W + wi + 4];
            uint32_t al0 = XlW[(rb + lq    )*X_STRIDE_W + wi];
            uint32_t al1 = XlW[(rb + lq + 8)*X_STRIDE_W + wi];
            uint32_t al2 = XlW[(rb + lq    )*X_STRIDE_W + wi + 4];
            uint32_t al3 = XlW[(rb + lq + 8)*X_STRIDE_W + wi + 4];
            #pragma unroll
            for (int nb = 0; nb < 8; nb++) {
                uint32_t bh0 = WhW[(nb*8 + lq)*X_STRIDE_W + wi];
                uint32_t bh1 = WhW[(nb*8 + lq)*X_STRIDE_W + wi + 4];
                uint32_t bl0 = WlW[(nb*8 + lq)*X_STRIDE_W + wi];
                uint32_t bl1 = WlW[(nb*8 + lq)*X_STRIDE_W + wi + 4];
                mma_bf16(acc[nb], ah0, ah1, ah2, ah3, bh0, bh1);
                mma_bf16(acc[nb], ah0, ah1, ah2, ah3, bl0, bl1);
                mma_bf16(acc[nb], al0, al1, al2, al3, bh0, bh1);
            }
        }
    }

    // ---- epilogue ----
    const int r0 = row0 + rb + lq;
    const int b  = r0 >> 11;
    const int n0 = r0 & 2047;
    const int n1 = n0 + 8;
    const int g  = b*HH + h;
    const size_t base0 = ((size_t)g*NN + n0)*DD;
    const size_t base1 = ((size_t)g*NN + n1)*DD;

    if (ot == 2) {
        #pragma unroll
        for (int nb = 0; nb < 8; nb++) {
            int col = nb*8 + 2*cq;
            *(float2*)&g_v[base0 + col] = make_float2(acc[nb][0], acc[nb][1]);
            *(float2*)&g_v[base1 + col] = make_float2(acc[nb][2], acc[nb][3]);
        }
    } else {
        const int eb = g & 3;                        // g % B  (batch-minor!)
        const float s  = (ot == 0) ? 0.125f : 1.0f;
        const float f0 = edge[eb*NN + n0] * s;
        const float f1 = edge[eb*NN + n1] * s;
        __nv_bfloat16* __restrict__ dh = (ot == 0) ? g_qh : g_kh;
        __nv_bfloat16* __restrict__ dl = (ot == 0) ? g_ql : g_kl;
        #pragma unroll
        for (int nb = 0; nb < 8; nb++) {
            int col = nb*8 + 2*cq;
            float v00 = acc[nb][0]*f0, v01 = acc[nb][1]*f0;
            float v10 = acc[nb][2]*f1, v11 = acc[nb][3]*f1;
            __nv_bfloat16 h00, l00, h01, l01, h10, l10, h11, l11;
            bf16_split(v00, h00, l00); bf16_split(v01, h01, l01);
            bf16_split(v10, h10, l10); bf16_split(v11, h11, l11);
            __nv_bfloat162 t;
            t.x = h00; t.y = h01; *(__nv_bfloat162*)&dh[base0 + col] = t;
            t.x = l00; t.y = l01; *(__nv_bfloat162*)&dl[base0 + col] = t;
            t.x = h10; t.y = h11; *(__nv_bfloat162*)&dh[base1 + col] = t;
            t.x = l10; t.y = l11; *(__nv_bfloat162*)&dl[base1 + col] = t;
        }
    }
}

// ---------------------------------------------------------------------------
// Kernel 1b: V transpose + bf16 hi/lo split:  (g,n,d) f32 -> (g,d,n) bf16 x2.
// ---------------------------------------------------------------------------
__global__ void __launch_bounds__(256)
vtrans_kernel()
{
    __shared__ float T[64][65];
    const int tid = threadIdx.x;
    const int nt  = blockIdx.x;      // n-tile of 64
    const int g   = blockIdx.y;

    #pragma unroll
    for (int i = 0; i < 16; i++) {
        int e = tid + 256*i;
        int d = e & 63, n = e >> 6;
        T[n][d] = g_v[((size_t)g*NN + nt*64 + n)*DD + d];
    }
    __syncthreads();
    #pragma unroll
    for (int i = 0; i < 8; i++) {
        int e = tid + 256*i;
        int np = e & 31, d = e >> 5;
        int n = 2*np;
        float v0 = T[n][d], v1 = T[n+1][d];
        __nv_bfloat16 h0, l0, h1, l1;
        bf16_split(v0, h0, l0); bf16_split(v1, h1, l1);
        size_t o = ((size_t)g*DD + d)*NN + nt*64 + n;
        __nv_bfloat162 t;
        t.x = h0; t.y = h1; *(__nv_bfloat162*)&g_vth[o] = t;
        t.x = l0; t.y = l1; *(__nv_bfloat162*)&g_vtl[o] = t;
    }
}

// ---------------------------------------------------------------------------
// Kernel 2: flash attention, hi/lo bf16 3-chain, ldmatrix.x4 fragment loads.
// Epilogue writes O as bf16 hi/lo into merged (b*N+n, h*64+d) layout.
// ---------------------------------------------------------------------------
#define QK_STRIDE_W 36          // words per row (144 B: 128 data + 16 pad)
#define V_STRIDE_W  68          // words per row (272 B: 256 data + 16 pad)
#define QH_B 0
#define QL_B 18432
#define KH_B 36864
#define KL_B 55296
#define VH_B 73728
#define VL_B 91136
#define ATTN_SMEM 108544

__global__ void __launch_bounds__(256, 2)
attn_mma_kernel()
{
    extern __shared__ char smx[];
    const uint32_t sb = smem_u32(smx);

    const int tid  = threadIdx.x;
    const int w    = tid >> 5;
    const int lane = tid & 31;
    const int lq   = lane >> 2;
    const int cq   = lane & 3;
    const int l7   = lane & 7;
    const int lb3  = (lane >> 3) & 1;
    const int lb4  = lane >> 4;
    const int g    = blockIdx.y;
    const int i0   = blockIdx.x * 128;
    const int rb   = w * 16;

    // ldmatrix lane-address bases
    const uint32_t qh_base = sb + QH_B + (rb + 8*lb3 + l7)*144 + 16*lb4;
    const uint32_t ql_base = qh_base + (QL_B - QH_B);
    const uint32_t kh_base = sb + KH_B + (lb4*8 + l7)*144 + 16*lb3;
    const uint32_t kl_base = kh_base + (KL_B - KH_B);
    const uint32_t vh_base = sb + VH_B + (lb4*8 + l7)*272 + 16*lb3;
    const uint32_t vl_base = vh_base + (VL_B - VH_B);

    // ---- prologue: Q tile via cp.async (pre-folded bf16 hi/lo) ----
    #pragma unroll
    for (int i = 0; i < 4; i++) {
        int c = tid + 256*i;
        int r = c >> 3, cc = c & 7;
        cp16(sb + QH_B + r*144 + cc*16, g_qh + ((size_t)g*NN + i0 + r)*DD + cc*8);
        cp16(sb + QL_B + r*144 + cc*16, g_ql + ((size_t)g*NN + i0 + r)*DD + cc*8);
    }
    CP_COMMIT();

    float Oacc[8][4] = {};
    float lsum0 = 0.0f, lsum1 = 0.0f;

    for (int jt = 0; jt < 16; jt++) {
        const int j0 = jt * 128;
        __syncthreads();

        #pragma unroll
        for (int i = 0; i < 4; i++) {
            int c = tid + 256*i;
            int j = c >> 3, cc = c & 7;
            cp16(sb + KH_B + j*144 + cc*16, g_kh + ((size_t)g*NN + j0 + j)*DD + cc*8);
            cp16(sb + KL_B + j*144 + cc*16, g_kl + ((size_t)g*NN + j0 + j)*DD + cc*8);
        }
        #pragma unroll
        for (int i = 0; i < 4; i++) {
            int c = tid + 256*i;
            int d = c >> 4, cc = c & 15;
            cp16(sb + VH_B + d*272 + cc*16, g_vth + ((size_t)g*DD + d)*NN + j0 + cc*8);
            cp16(sb + VL_B + d*272 + cc*16, g_vtl + ((size_t)g*DD + d)*NN + j0 + cc*8);
        }
        CP_COMMIT();
        CP_WAIT0();
        __syncthreads();

        // ---- S = Q K^T : 3-chain, ldmatrix fragments ----
        float S[16][4];
        #pragma unroll
        for (int nb = 0; nb < 16; nb++)
            #pragma unroll
            for (int i = 0; i < 4; i++) S[nb][i] = 0.0f;

        #pragma unroll
        for (int kc = 0; kc < 4; kc++) {
            uint32_t ah0, ah1, ah2, ah3, al0, al1, al2, al3;
            ldm_x4(ah0, ah1, ah2, ah3, qh_base + kc*32);
            ldm_x4(al0, al1, al2, al3, ql_base + kc*32);
            #pragma unroll
            for (int nbp = 0; nbp < 8; nbp++) {
                uint32_t h0, h1, h2, h3, u0, u1, u2, u3;
                ldm_x4(h0, h1, h2, h3, kh_base + nbp*2304 + kc*32);
                ldm_x4(u0, u1, u2, u3, kl_base + nbp*2304 + kc*32);
                mma_bf16(S[2*nbp  ], ah0, ah1, ah2, ah3, h0, h1);
                mma_bf16(S[2*nbp  ], ah0, ah1, ah2, ah3, u0, u1);
                mma_bf16(S[2*nbp  ], al0, al1, al2, al3, h0, h1);
                mma_bf16(S[2*nbp+1], ah0, ah1, ah2, ah3, h2, h3);
                mma_bf16(S[2*nbp+1], ah0, ah1, ah2, ah3, u2, u3);
                mma_bf16(S[2*nbp+1], al0, al1, al2, al3, h2, h3);
            }
        }

        // ---- softmax (logits bounded, no max needed) ----
        #pragma unroll
        for (int nb = 0; nb < 16; nb++) {
            float p0 = __expf(S[nb][0]);
            float p1 = __expf(S[nb][1]);
            float p2 = __expf(S[nb][2]);
            float p3 = __expf(S[nb][3]);
            S[nb][0] = p0; S[nb][1] = p1; S[nb][2] = p2; S[nb][3] = p3;
            lsum0 += p0 + p1;
            lsum1 += p2 + p3;
        }

        // ---- O += P V : 3-chain, P from regs, V via ldmatrix ----
        #pragma unroll
        for (int kc = 0; kc < 8; kc++) {
            float p00 = S[2*kc][0],   p01 = S[2*kc][1];
            float p02 = S[2*kc][2],   p03 = S[2*kc][3];
            float p10 = S[2*kc+1][0], p11 = S[2*kc+1][1];
            float p12 = S[2*kc+1][2], p13 = S[2*kc+1][3];
            uint32_t ah0 = pack_bf16(p00, p01);
            uint32_t ah1 = pack_bf16(p02, p03);
            uint32_t ah2 = pack_bf16(p10, p11);
            uint32_t ah3 = pack_bf16(p12, p13);
            __nv_bfloat162 h0 = *(__nv_bfloat162*)&ah0;
            __nv_bfloat162 h1 = *(__nv_bfloat162*)&ah1;
            __nv_bfloat162 h2 = *(__nv_bfloat162*)&ah2;
            __nv_bfloat162 h3 = *(__nv_bfloat162*)&ah3;
            uint32_t al0 = pack_bf16(p00 - __bfloat162float(h0.x),
                                     p01 - __bfloat162float(h0.y));
            uint32_t al1 = pack_bf16(p02 - __bfloat162float(h1.x),
                                     p03 - __bfloat162float(h1.y));
            uint32_t al2 = pack_bf16(p10 - __bfloat162float(h2.x),
                                     p11 - __bfloat162float(h2.y));
            uint32_t al3 = pack_bf16(p12 - __bfloat162float(h3.x),
                                     p13 - __bfloat162float(h3.y));
            #pragma unroll
            for (int ndp = 0; ndp < 4; ndp++) {
                uint32_t b0, b1, b2, b3, u0, u1, u2, u3;
                ldm_x4(b0, b1, b2, b3, vh_base + ndp*4352 + kc*32);
                ldm_x4(u0, u1, u2, u3, vl_base + ndp*4352 + kc*32);
                mma_bf16(Oacc[2*ndp  ], ah0, ah1, ah2, ah3, b0, b1);
                mma_bf16(Oacc[2*ndp  ], ah0, ah1, ah2, ah3, u0, u1);
                mma_bf16(Oacc[2*ndp  ], al0, al1, al2, al3, b0, b1);
                mma_bf16(Oacc[2*ndp+1], ah0, ah1, ah2, ah3, b2, b3);
                mma_bf16(Oacc[2*ndp+1], ah0, ah1, ah2, ah3, u2, u3);
                mma_bf16(Oacc[2*ndp+1], al0, al1, al2, al3, b2, b3);
            }
        }
    }

    // ---- reduce row sums across the quad sharing each row ----
    lsum0 += __shfl_xor_sync(0xFFFFFFFF, lsum0, 1);
    lsum0 += __shfl_xor_sync(0xFFFFFFFF, lsum0, 2);
    lsum1 += __shfl_xor_sync(0xFFFFFFFF, lsum1, 1);
    lsum1 += __shfl_xor_sync(0xFFFFFFFF, lsum1, 2);
    const float inv0 = 1.0f / lsum0;
    const float inv1 = 1.0f / lsum1;

    // ---- write O as bf16 hi/lo into merged layout (row, h*64+d) ----
    const int b = g / HH, h = g % HH;
    const int rowg0 = b*NN + i0 + rb + lq;
    const int rowg1 = rowg0 + 8;
    #pragma unroll
    for (int nd = 0; nd < 8; nd++) {
        int col = h*64 + nd*8 + 2*cq;
        float v00 = Oacc[nd][0]*inv0, v01 = Oacc[nd][1]*inv0;
        float v10 = Oacc[nd][2]*inv1, v11 = Oacc[nd][3]*inv1;
        __nv_bfloat16 h00, l00, h01, l01, h10, l10, h11, l11;
        bf16_split(v00, h00, l00); bf16_split(v01, h01, l01);
        bf16_split(v10, h10, l10); bf16_split(v11, h11, l11);
        __nv_bfloat162 t;
        t.x = h00; t.y = h01; *(__nv_bfloat162*)&g_oh[(size_t)rowg0*CC + col] = t;
        t.x = l00; t.y = l01; *(__nv_bfloat162*)&g_ol[(size_t)rowg0*CC + col] = t;
        t.x = h10; t.y = h11; *(__nv_bfloat162*)&g_oh[(size_t)rowg1*CC + col] = t;
        t.x = l10; t.y = l11; *(__nv_bfloat162*)&g_ol[(size_t)rowg1*CC + col] = t;
    }
}

// ---------------------------------------------------------------------------
// Kernel 3: output projection via bf16 hi/lo 3-chain MMA + bias.
// A = pre-split attn output (cp.async), B = Wo split in-kernel.
// ---------------------------------------------------------------------------
__global__ void __launch_bounds__(256)
oproj_mma_kernel(const float* __restrict__ Wo,
                 const float* __restrict__ bo,
                 float* __restrict__ out)
{
    __shared__ uint32_t smq[128*X_STRIDE_W*2 + 64*X_STRIDE_W*2];
    const uint32_t sb = smem_u32(smq);
    uint32_t* XhW = smq;
    uint32_t* XlW = XhW + 128*X_STRIDE_W;
    uint32_t* WhW = XlW + 128*X_STRIDE_W;
    uint32_t* WlW = WhW + 64*X_STRIDE_W;
    __nv_bfloat16* Wh = (__nv_bfloat16*)WhW;
    __nv_bfloat16* Wl = (__nv_bfloat16*)WlW;
    const uint32_t XH_OFF = 0;
    const uint32_t XL_OFF = 128*X_STRIDE_W*4;

    const int tid  = threadIdx.x;
    const int wid  = tid >> 5;
    const int lane = tid & 31;
    const int lq   = lane >> 2;
    const int cq   = lane & 3;
    const int rb   = wid * 16;
    const int c0   = blockIdx.x * 64;
    const int row0 = blockIdx.y * 128;

    float acc[8][4] = {};

    for (int k0 = 0; k0 < CC; k0 += 32) {
        __syncthreads();
        // A tile via cp.async: 128 rows x 32 halves (64B) per buffer
        #pragma unroll
        for (int i = 0; i < 2; i++) {
            int c = tid + 256*i;
            int r = c >> 2, cc = c & 3;
            cp16(sb + XH_OFF + r*80 + cc*16, g_oh + (size_t)(row0 + r)*CC + k0 + cc*8);
            cp16(sb + XL_OFF + r*80 + cc*16, g_ol + (size_t)(row0 + r)*CC + k0 + cc*8);
        }
        // W tile: split fp32 -> hi/lo, stored [n][kk]
        #pragma unroll
        for (int i = 0; i < 8; i++) {
            int e = tid + 256*i;
            int n = e & 63, kk = e >> 6;
            float v = Wo[(k0 + kk)*CC + c0 + n];
            __nv_bfloat16 hh, ll; bf16_split(v, hh, ll);
            Wh[n*40 + kk] = hh;
            Wl[n*40 + kk] = ll;
        }
        CP_COMMIT();
        CP_WAIT0();
        __syncthreads();

        #pragma unroll
        for (int kc = 0; kc < 2; kc++) {
            const int wi = kc*8 + cq;
            uint32_t ah0 = XhW[(rb + lq    )*X_STRIDE_W + wi];
            uint32_t ah1 = XhW[(rb + lq + 8)*X_STRIDE_W + wi];
            uint32_t ah2 = XhW[(rb + lq    )*X_STRIDE_W + wi + 4];
            uint32_t ah3 = XhW[(rb + lq + 8)*X_STRIDE_W + wi + 4];
            uint32_t al0 = XlW[(rb + lq    )*X_STRIDE_W + wi];
            uint32_t al1 = XlW[(rb + lq + 8)*X_STRIDE_W + wi];
            uint32_t al2 = XlW[(rb + lq    )*X_STRIDE_W + wi + 4];
            uint32_t al3 = XlW[(rb + lq + 8)*X_STRIDE_W + wi + 4];
            #pragma unroll
            for (int nb = 0; nb < 8; nb++) {
                uint32_t bh0 = WhW[(nb*8 + lq)*X_STRIDE_W + wi];
                uint32_t bh1 = WhW[(nb*8 + lq)*X_STRIDE_W + wi + 4];
                uint32_t bl0 = WlW[(nb*8 + lq)*X_STRIDE_W + wi];
                uint32_t bl1 = WlW[(nb*8 + lq)*X_STRIDE_W + wi + 4];
                mma_bf16(acc[nb], ah0, ah1, ah2, ah3, bh0, bh1);
                mma_bf16(acc[nb], ah0, ah1, ah2, ah3, bl0, bl1);
                mma_bf16(acc[nb], al0, al1, al2, al3, bh0, bh1);
            }
        }
    }

    // ---- epilogue: add bias, write fp32 out ----
    const int r0 = row0 + rb + lq;
    const int r1 = r0 + 8;
    #pragma unroll
    for (int nb = 0; nb < 8; nb++) {
        int col = c0 + nb*8 + 2*cq;
        float b0v = bo[col], b1v = bo[col+1];
        *(float2*)&out[(size_t)r0*CC + col] =
            make_float2(acc[nb][0] + b0v, acc[nb][1] + b1v);
        *(float2*)&out[(size_t)r1*CC + col] =
            make_float2(acc[nb][2] + b0v, acc[nb][3] + b1v);
    }
}

// ---------------------------------------------------------------------------
extern "C" void kernel_launch(void* const* d_in, const int* in_sizes, int n_in,
                              void* d_out, int out_size)
{
    const float* x    = (const float*)d_in[0];
    const float* edge = (const float*)d_in[1];
    const float* Wq   = (const float*)d_in[2];
    const float* Wk   = (const float*)d_in[3];
    const float* Wv   = (const float*)d_in[4];
    const float* Wo   = (const float*)d_in[5];
    const float* bo   = (const float*)d_in[6];
    float* out = (float*)d_out;

    qkv_mma_kernel<<<dim3(15, 64), 256>>>(x, Wq, Wk, Wv, edge);
    vtrans_kernel<<<dim3(32, GG), 256>>>();

    cudaFuncSetAttribute(attn_mma_kernel,
                         cudaFuncAttributeMaxDynamicSharedMemorySize, ATTN_SMEM);
    attn_mma_kernel<<<dim3(16, GG), 256, ATTN_SMEM>>>();

    oproj_mma_kernel<<<dim3(5, 64), 256>>>(Wo, bo, out);
}

// round 12
// speedup vs baseline: 1.4037x; 1.4037x over previous
#include <cuda_runtime.h>
#include <cuda_bf16.h>
#include <cstdint>

#define BB 4
#define NN 2048
#define CC 320
#define HH 5
#define DD 64
#define GG (BB*HH)      // 20
#define ROWS (BB*NN)    // 8192

// scratch (allocation-free rule: __device__ globals)
__device__ __nv_bfloat16 g_qh[GG*NN*DD];   // folded 0.125*e_i, hi
__device__ __nv_bfloat16 g_ql[GG*NN*DD];   // lo
__device__ __nv_bfloat16 g_kh[GG*NN*DD];   // folded e_j, hi
__device__ __nv_bfloat16 g_kl[GG*NN*DD];   // lo
__device__ float         g_v [GG*NN*DD];   // fp32 (pre-transpose)
__device__ __nv_bfloat16 g_vth[GG*DD*NN];  // transposed (g,d,n), hi
__device__ __nv_bfloat16 g_vtl[GG*DD*NN];  // lo
__device__ __nv_bfloat16 g_oh[ROWS*CC];    // attn out, merged (b*N+n, h*64+d), hi
__device__ __nv_bfloat16 g_ol[ROWS*CC];    // lo

// ============================ helpers ======================================
__device__ __forceinline__ void mma_bf16(float* d,
    uint32_t a0, uint32_t a1, uint32_t a2, uint32_t a3,
    uint32_t b0, uint32_t b1)
{
    asm volatile(
        "mma.sync.aligned.m16n8k16.row.col.f32.bf16.bf16.f32 "
        "{%0,%1,%2,%3}, {%4,%5,%6,%7}, {%8,%9}, {%0,%1,%2,%3};"
        : "+f"(d[0]), "+f"(d[1]), "+f"(d[2]), "+f"(d[3])
        : "r"(a0), "r"(a1), "r"(a2), "r"(a3), "r"(b0), "r"(b1));
}

__device__ __forceinline__ void bf16_split(float v, __nv_bfloat16& h, __nv_bfloat16& l) {
    h = __float2bfloat16(v);
    l = __float2bfloat16(v - __bfloat162float(h));
}

__device__ __forceinline__ uint32_t pack_bf16(float a, float b) {
    __nv_bfloat162 t = __floats2bfloat162_rn(a, b);
    return *(uint32_t*)&t;
}

__device__ __forceinline__ uint32_t smem_u32(const void* p) {
    uint32_t a;
    asm("{ .reg .u64 t; cvta.to.shared.u64 t, %1; cvt.u32.u64 %0, t; }"
        : "=r"(a) : "l"(p));
    return a;
}

__device__ __forceinline__ void cp16(uint32_t dst, const void* src) {
    asm volatile("cp.async.cg.shared.global [%0], [%1], 16;"
                 :: "r"(dst), "l"(src) : "memory");
}
#define CP_COMMIT() asm volatile("cp.async.commit_group;" ::: "memory")
#define CP_WAIT0()  asm volatile("cp.async.wait_group 0;" ::: "memory")

// ---------------------------------------------------------------------------
// Kernel 1: QKV projection via bf16 hi/lo 3-chain MMA (verified R7).
// ---------------------------------------------------------------------------
#define X_STRIDE_W 20      // words per row (40 halves: 32 data + 8 pad)
__global__ void __launch_bounds__(256)
qkv_mma_kernel(const float* __restrict__ x,
               const float* __restrict__ Wq,
               const float* __restrict__ Wk,
               const float* __restrict__ Wv,
               const float* __restrict__ edge)
{
    __shared__ uint32_t smq[128*X_STRIDE_W*2 + 64*X_STRIDE_W*2];
    uint32_t* XhW = smq;
    uint32_t* XlW = XhW + 128*X_STRIDE_W;
    uint32_t* WhW = XlW + 128*X_STRIDE_W;
    uint32_t* WlW = WhW + 64*X_STRIDE_W;
    __nv_bfloat16* Xh = (__nv_bfloat16*)XhW;
    __nv_bfloat16* Xl = (__nv_bfloat16*)XlW;
    __nv_bfloat16* Wh = (__nv_bfloat16*)WhW;
    __nv_bfloat16* Wl = (__nv_bfloat16*)WlW;

    const int tid  = threadIdx.x;
    const int wid  = tid >> 5;
    const int lane = tid & 31;
    const int lq   = lane >> 2;
    const int cq   = lane & 3;
    const int rb   = wid * 16;
    const int colt = blockIdx.x;       // 0..14
    const int ot   = colt / 5;         // 0=q 1=k 2=v
    const int h    = colt % 5;
    const int wc0  = h * 64;
    const int row0 = blockIdx.y * 128;
    const float* __restrict__ W = (ot == 0) ? Wq : (ot == 1) ? Wk : Wv;

    float acc[8][4] = {};

    for (int k0 = 0; k0 < CC; k0 += 32) {
        __syncthreads();
        #pragma unroll
        for (int i = 0; i < 16; i++) {
            int e = tid + 256*i;
            int kk = e & 31, r = e >> 5;
            float v = x[(row0 + r)*CC + k0 + kk];
            __nv_bfloat16 hh, ll; bf16_split(v, hh, ll);
            Xh[r*40 + kk] = hh;
            Xl[r*40 + kk] = ll;
        }
        #pragma unroll
        for (int i = 0; i < 8; i++) {
            int e = tid + 256*i;
            int n = e & 63, kk = e >> 6;
            float v = W[(k0 + kk)*CC + wc0 + n];
            __nv_bfloat16 hh, ll; bf16_split(v, hh, ll);
            Wh[n*40 + kk] = hh;
            Wl[n*40 + kk] = ll;
        }
        __syncthreads();

        #pragma unroll
        for (int kc = 0; kc < 2; kc++) {
            const int wi = kc*8 + cq;
            uint32_t ah0 = XhW[(rb + lq    )*X_STRIDE_W + wi];
            uint32_t ah1 = XhW[(rb + lq + 8)*X_STRIDE_W + wi];
            uint32_t ah2 = XhW[(rb + lq    )*X_STRIDE_W + wi + 4];
            uint32_t ah3 = XhW[(rb + lq + 8)*X_STRIDE_W + wi + 4];
            uint32_t al0 = XlW[(rb + lq    )*X_STRIDE_W + wi];
            uint32_t al1 = XlW[(rb + lq + 8)*X_STRIDE_W + wi];
            uint32_t al2 = XlW[(rb + lq    )*X_STRIDE_W + wi + 4];
            uint32_t al3 = XlW[(rb + lq + 8)*X_STRIDE_W + wi + 4];
            #pragma unroll
            for (int nb = 0; nb < 8; nb++) {
                uint32_t bh0 = WhW[(nb*8 + lq)*X_STRIDE_W + wi];
                uint32_t bh1 = WhW[(nb*8 + lq)*X_STRIDE_W + wi + 4];
                uint32_t bl0 = WlW[(nb*8 + lq)*X_STRIDE_W + wi];
                uint32_t bl1 = WlW[(nb*8 + lq)*X_STRIDE_W + wi + 4];
                mma_bf16(acc[nb], ah0, ah1, ah2, ah3, bh0, bh1);
                mma_bf16(acc[nb], ah0, ah1, ah2, ah3, bl0, bl1);
                mma_bf16(acc[nb], al0, al1, al2, al3, bh0, bh1);
            }
        }
    }

    // ---- epilogue ----
    const int r0 = row0 + rb + lq;
    const int b  = r0 >> 11;
    const int n0 = r0 & 2047;
    const int n1 = n0 + 8;
    const int g  = b*HH + h;
    const size_t base0 = ((size_t)g*NN + n0)*DD;
    const size_t base1 = ((size_t)g*NN + n1)*DD;

    if (ot == 2) {
        #pragma unroll
        for (int nb = 0; nb < 8; nb++) {
            int col = nb*8 + 2*cq;
            *(float2*)&g_v[base0 + col] = make_float2(acc[nb][0], acc[nb][1]);
            *(float2*)&g_v[base1 + col] = make_float2(acc[nb][2], acc[nb][3]);
        }
    } else {
        const int eb = g & 3;                        // g % B  (batch-minor!)
        const float s  = (ot == 0) ? 0.125f : 1.0f;
        const float f0 = edge[eb*NN + n0] * s;
        const float f1 = edge[eb*NN + n1] * s;
        __nv_bfloat16* __restrict__ dh = (ot == 0) ? g_qh : g_kh;
        __nv_bfloat16* __restrict__ dl = (ot == 0) ? g_ql : g_kl;
        #pragma unroll
        for (int nb = 0; nb < 8; nb++) {
            int col = nb*8 + 2*cq;
            float v00 = acc[nb][0]*f0, v01 = acc[nb][1]*f0;
            float v10 = acc[nb][2]*f1, v11 = acc[nb][3]*f1;
            __nv_bfloat16 h00, l00, h01, l01, h10, l10, h11, l11;
            bf16_split(v00, h00, l00); bf16_split(v01, h01, l01);
            bf16_split(v10, h10, l10); bf16_split(v11, h11, l11);
            __nv_bfloat162 t;
            t.x = h00; t.y = h01; *(__nv_bfloat162*)&dh[base0 + col] = t;
            t.x = l00; t.y = l01; *(__nv_bfloat162*)&dl[base0 + col] = t;
            t.x = h10; t.y = h11; *(__nv_bfloat162*)&dh[base1 + col] = t;
            t.x = l10; t.y = l11; *(__nv_bfloat162*)&dl[base1 + col] = t;
        }
    }
}

// ---------------------------------------------------------------------------
// Kernel 1b: V transpose + bf16 hi/lo split:  (g,n,d) f32 -> (g,d,n) bf16 x2.
// ---------------------------------------------------------------------------
__global__ void __launch_bounds__(256)
vtrans_kernel()
{
    __shared__ float T[64][65];
    const int tid = threadIdx.x;
    const int nt  = blockIdx.x;      // n-tile of 64
    const int g   = blockIdx.y;

    #pragma unroll
    for (int i = 0; i < 16; i++) {
        int e = tid + 256*i;
        int d = e & 63, n = e >> 6;
        T[n][d] = g_v[((size_t)g*NN + nt*64 + n)*DD + d];
    }
    __syncthreads();
    #pragma unroll
    for (int i = 0; i < 8; i++) {
        int e = tid + 256*i;
        int np = e & 31, d = e >> 5;
        int n = 2*np;
        float v0 = T[n][d], v1 = T[n+1][d];
        __nv_bfloat16 h0, l0, h1, l1;
        bf16_split(v0, h0, l0); bf16_split(v1, h1, l1);
        size_t o = ((size_t)g*DD + d)*NN + nt*64 + n;
        __nv_bfloat162 t;
        t.x = h0; t.y = h1; *(__nv_bfloat162*)&g_vth[o] = t;
        t.x = l0; t.y = l1; *(__nv_bfloat162*)&g_vtl[o] = t;
    }
}

// ---------------------------------------------------------------------------
// Kernel 2: flash attention, hi/lo bf16 3-chain. R7 manual-LDS fragment loads
// (proven fast; ldmatrix variant spilled under the 128-reg/thread cap).
// Epilogue writes O as bf16 hi/lo into merged (b*N+n, h*64+d) layout.
// ---------------------------------------------------------------------------
#define QK_STRIDE_W 36          // words per row (144 B: 128 data + 16 pad)
#define V_STRIDE_W  68          // words per row (272 B: 256 data + 16 pad)
#define QH_B 0
#define QL_B 18432
#define KH_B 36864
#define KL_B 55296
#define VH_B 73728
#define VL_B 91136
#define ATTN_SMEM 108544

__global__ void __launch_bounds__(256, 2)
attn_mma_kernel()
{
    extern __shared__ char smx[];
    const uint32_t sb = smem_u32(smx);
    uint32_t* QhW = (uint32_t*)(smx + QH_B);
    uint32_t* QlW = (uint32_t*)(smx + QL_B);
    uint32_t* KhW = (uint32_t*)(smx + KH_B);
    uint32_t* KlW = (uint32_t*)(smx + KL_B);
    uint32_t* VhW = (uint32_t*)(smx + VH_B);
    uint32_t* VlW = (uint32_t*)(smx + VL_B);

    const int tid  = threadIdx.x;
    const int w    = tid >> 5;
    const int lane = tid & 31;
    const int lq   = lane >> 2;
    const int cq   = lane & 3;
    const int g    = blockIdx.y;
    const int i0   = blockIdx.x * 128;
    const int rb   = w * 16;

    // ---- prologue: Q tile via cp.async (pre-folded bf16 hi/lo) ----
    #pragma unroll
    for (int i = 0; i < 4; i++) {
        int c = tid + 256*i;
        int r = c >> 3, cc = c & 7;
        cp16(sb + QH_B + r*144 + cc*16, g_qh + ((size_t)g*NN + i0 + r)*DD + cc*8);
        cp16(sb + QL_B + r*144 + cc*16, g_ql + ((size_t)g*NN + i0 + r)*DD + cc*8);
    }
    CP_COMMIT();

    float Oacc[8][4] = {};
    float lsum0 = 0.0f, lsum1 = 0.0f;

    for (int jt = 0; jt < 16; jt++) {
        const int j0 = jt * 128;
        __syncthreads();

        #pragma unroll
        for (int i = 0; i < 4; i++) {
            int c = tid + 256*i;
            int j = c >> 3, cc = c & 7;
            cp16(sb + KH_B + j*144 + cc*16, g_kh + ((size_t)g*NN + j0 + j)*DD + cc*8);
            cp16(sb + KL_B + j*144 + cc*16, g_kl + ((size_t)g*NN + j0 + j)*DD + cc*8);
        }
        #pragma unroll
        for (int i = 0; i < 4; i++) {
            int c = tid + 256*i;
            int d = c >> 4, cc = c & 15;
            cp16(sb + VH_B + d*272 + cc*16, g_vth + ((size_t)g*DD + d)*NN + j0 + cc*8);
            cp16(sb + VL_B + d*272 + cc*16, g_vtl + ((size_t)g*DD + d)*NN + j0 + cc*8);
        }
        CP_COMMIT();
        CP_WAIT0();
        __syncthreads();

        // ---- S = Q K^T : 3-chain, manual LDS fragment loads (R7) ----
        float S[16][4];
        #pragma unroll
        for (int nb = 0; nb < 16; nb++)
            #pragma unroll
            for (int i = 0; i < 4; i++) S[nb][i] = 0.0f;

        #pragma unroll
        for (int kc = 0; kc < 4; kc++) {
            const int wi = kc*8 + cq;
            uint32_t ah0 = QhW[(rb + lq    )*QK_STRIDE_W + wi];
            uint32_t ah1 = QhW[(rb + lq + 8)*QK_STRIDE_W + wi];
            uint32_t ah2 = QhW[(rb + lq    )*QK_STRIDE_W + wi + 4];
            uint32_t ah3 = QhW[(rb + lq + 8)*QK_STRIDE_W + wi + 4];
            uint32_t al0 = QlW[(rb + lq    )*QK_STRIDE_W + wi];
            uint32_t al1 = QlW[(rb + lq + 8)*QK_STRIDE_W + wi];
            uint32_t al2 = QlW[(rb + lq    )*QK_STRIDE_W + wi + 4];
            uint32_t al3 = QlW[(rb + lq + 8)*QK_STRIDE_W + wi + 4];
            #pragma unroll
            for (int nb = 0; nb < 16; nb++) {
                uint32_t bh0 = KhW[(nb*8 + lq)*QK_STRIDE_W + wi];
                uint32_t bh1 = KhW[(nb*8 + lq)*QK_STRIDE_W + wi + 4];
                uint32_t bl0 = KlW[(nb*8 + lq)*QK_STRIDE_W + wi];
                uint32_t bl1 = KlW[(nb*8 + lq)*QK_STRIDE_W + wi + 4];
                mma_bf16(S[nb], ah0, ah1, ah2, ah3, bh0, bh1);
                mma_bf16(S[nb], ah0, ah1, ah2, ah3, bl0, bl1);
                mma_bf16(S[nb], al0, al1, al2, al3, bh0, bh1);
            }
        }

        // ---- softmax (logits bounded, no max needed) ----
        #pragma unroll
        for (int nb = 0; nb < 16; nb++) {
            float p0 = __expf(S[nb][0]);
            float p1 = __expf(S[nb][1]);
            float p2 = __expf(S[nb][2]);
            float p3 = __expf(S[nb][3]);
            S[nb][0] = p0; S[nb][1] = p1; S[nb][2] = p2; S[nb][3] = p3;
            lsum0 += p0 + p1;
            lsum1 += p2 + p3;
        }

        // ---- O += P V : 3-chain, P from regs, V via manual LDS (R7) ----
        #pragma unroll
        for (int kc = 0; kc < 8; kc++) {
            float p00 = S[2*kc][0],   p01 = S[2*kc][1];
            float p02 = S[2*kc][2],   p03 = S[2*kc][3];
            float p10 = S[2*kc+1][0], p11 = S[2*kc+1][1];
            float p12 = S[2*kc+1][2], p13 = S[2*kc+1][3];
            uint32_t ah0 = pack_bf16(p00, p01);
            uint32_t ah1 = pack_bf16(p02, p03);
            uint32_t ah2 = pack_bf16(p10, p11);
            uint32_t ah3 = pack_bf16(p12, p13);
            __nv_bfloat162 h0 = *(__nv_bfloat162*)&ah0;
            __nv_bfloat162 h1 = *(__nv_bfloat162*)&ah1;
            __nv_bfloat162 h2 = *(__nv_bfloat162*)&ah2;
            __nv_bfloat162 h3 = *(__nv_bfloat162*)&ah3;
            uint32_t al0 = pack_bf16(p00 - __bfloat162float(h0.x),
                                     p01 - __bfloat162float(h0.y));
            uint32_t al1 = pack_bf16(p02 - __bfloat162float(h1.x),
                                     p03 - __bfloat162float(h1.y));
            uint32_t al2 = pack_bf16(p10 - __bfloat162float(h2.x),
                                     p11 - __bfloat162float(h2.y));
            uint32_t al3 = pack_bf16(p12 - __bfloat162float(h3.x),
                                     p13 - __bfloat162float(h3.y));
            const int wi = kc*8 + cq;
            #pragma unroll
            for (int nd = 0; nd < 8; nd++) {
                uint32_t bh0 = VhW[(nd*8 + lq)*V_STRIDE_W + wi];
                uint32_t bh1 = VhW[(nd*8 + lq)*V_STRIDE_W + wi + 4];
                uint32_t bl0 = VlW[(nd*8 + lq)*V_STRIDE_W + wi];
                uint32_t bl1 = VlW[(nd*8 + lq)*V_STRIDE_W + wi + 4];
                mma_bf16(Oacc[nd], ah0, ah1, ah2, ah3, bh0, bh1);
                mma_bf16(Oacc[nd], ah0, ah1, ah2, ah3, bl0, bl1);
                mma_bf16(Oacc[nd], al0, al1, al2, al3, bh0, bh1);
            }
        }
    }

    // ---- reduce row sums across the quad sharing each row ----
    lsum0 += __shfl_xor_sync(0xFFFFFFFF, lsum0, 1);
    lsum0 += __shfl_xor_sync(0xFFFFFFFF, lsum0, 2);
    lsum1 += __shfl_xor_sync(0xFFFFFFFF, lsum1, 1);
    lsum1 += __shfl_xor_sync(0xFFFFFFFF, lsum1, 2);
    const float inv0 = 1.0f / lsum0;
    const float inv1 = 1.0f / lsum1;

    // ---- write O as bf16 hi/lo into merged layout (row, h*64+d) ----
    const int b = g / HH, h = g % HH;
    const int rowg0 = b*NN + i0 + rb + lq;
    const int rowg1 = rowg0 + 8;
    #pragma unroll
    for (int nd = 0; nd < 8; nd++) {
        int col = h*64 + nd*8 + 2*cq;
        float v00 = Oacc[nd][0]*inv0, v01 = Oacc[nd][1]*inv0;
        float v10 = Oacc[nd][2]*inv1, v11 = Oacc[nd][3]*inv1;
        __nv_bfloat16 h00, l00, h01, l01, h10, l10, h11, l11;
        bf16_split(v00, h00, l00); bf16_split(v01, h01, l01);
        bf16_split(v10, h10, l10); bf16_split(v11, h11, l11);
        __nv_bfloat162 t;
        t.x = h00; t.y = h01; *(__nv_bfloat162*)&g_oh[(size_t)rowg0*CC + col] = t;
        t.x = l00; t.y = l01; *(__nv_bfloat162*)&g_ol[(size_t)rowg0*CC + col] = t;
        t.x = h10; t.y = h11; *(__nv_bfloat162*)&g_oh[(size_t)rowg1*CC + col] = t;
        t.x = l10; t.y = l11; *(__nv_bfloat162*)&g_ol[(size_t)rowg1*CC + col] = t;
    }
}

// ---------------------------------------------------------------------------
// Kernel 3: output projection via bf16 hi/lo 3-chain MMA + bias (verified R9).
// ---------------------------------------------------------------------------
__global__ void __launch_bounds__(256)
oproj_mma_kernel(const float* __restrict__ Wo,
                 const float* __restrict__ bo,
                 float* __restrict__ out)
{
    __shared__ uint32_t smq[128*X_STRIDE_W*2 + 64*X_STRIDE_W*2];
    const uint32_t sb = smem_u32(smq);
    uint32_t* XhW = smq;
    uint32_t* XlW = XhW + 128*X_STRIDE_W;
    uint32_t* WhW = XlW + 128*X_STRIDE_W;
    uint32_t* WlW = WhW + 64*X_STRIDE_W;
    __nv_bfloat16* Wh = (__nv_bfloat16*)WhW;
    __nv_bfloat16* Wl = (__nv_bfloat16*)WlW;
    const uint32_t XH_OFF = 0;
    const uint32_t XL_OFF = 128*X_STRIDE_W*4;

    const int tid  = threadIdx.x;
    const int wid  = tid >> 5;
    const int lane = tid & 31;
    const int lq   = lane >> 2;
    const int cq   = lane & 3;
    const int rb   = wid * 16;
    const int c0   = blockIdx.x * 64;
    const int row0 = blockIdx.y * 128;

    float acc[8][4] = {};

    for (int k0 = 0; k0 < CC; k0 += 32) {
        __syncthreads();
        // A tile via cp.async: 128 rows x 32 halves (64B) per buffer
        #pragma unroll
        for (int i = 0; i < 2; i++) {
            int c = tid + 256*i;
            int r = c >> 2, cc = c & 3;
            cp16(sb + XH_OFF + r*80 + cc*16, g_oh + (size_t)(row0 + r)*CC + k0 + cc*8);
            cp16(sb + XL_OFF + r*80 + cc*16, g_ol + (size_t)(row0 + r)*CC + k0 + cc*8);
        }
        // W tile: split fp32 -> hi/lo, stored [n][kk]
        #pragma unroll
        for (int i = 0; i < 8; i++) {
            int e = tid + 256*i;
            int n = e & 63, kk = e >> 6;
            float v = Wo[(k0 + kk)*CC + c0 + n];
            __nv_bfloat16 hh, ll; bf16_split(v, hh, ll);
            Wh[n*40 + kk] = hh;
            Wl[n*40 + kk] = ll;
        }
        CP_COMMIT();
        CP_WAIT0();
        __syncthreads();

        #pragma unroll
        for (int kc = 0; kc < 2; kc++) {
            const int wi = kc*8 + cq;
            uint32_t ah0 = XhW[(rb + lq    )*X_STRIDE_W + wi];
            uint32_t ah1 = XhW[(rb + lq + 8)*X_STRIDE_W + wi];
            uint32_t ah2 = XhW[(rb + lq    )*X_STRIDE_W + wi + 4];
            uint32_t ah3 = XhW[(rb + lq + 8)*X_STRIDE_W + wi + 4];
            uint32_t al0 = XlW[(rb + lq    )*X_STRIDE_W + wi];
            uint32_t al1 = XlW[(rb + lq + 8)*X_STRIDE_W + wi];
            uint32_t al2 = XlW[(rb + lq    )*X_STRIDE_W + wi + 4];
            uint32_t al3 = XlW[(rb + lq + 8)*X_STRIDE_W + wi + 4];
            #pragma unroll
            for (int nb = 0; nb < 8; nb++) {
                uint32_t bh0 = WhW[(nb*8 + lq)*X_STRIDE_W + wi];
                uint32_t bh1 = WhW[(nb*8 + lq)*X_STRIDE_W + wi + 4];
                uint32_t bl0 = WlW[(nb*8 + lq)*X_STRIDE_W + wi];
                uint32_t bl1 = WlW[(nb*8 + lq)*X_STRIDE_W + wi + 4];
                mma_bf16(acc[nb], ah0, ah1, ah2, ah3, bh0, bh1);
                mma_bf16(acc[nb], ah0, ah1, ah2, ah3, bl0, bl1);
                mma_bf16(acc[nb], al0, al1, al2, al3, bh0, bh1);
            }
        }
    }

    // ---- epilogue: add bias, write fp32 out ----
    const int r0 = row0 + rb + lq;
    const int r1 = r0 + 8;
    #pragma unroll
    for (int nb = 0; nb < 8; nb++) {
        int col = c0 + nb*8 + 2*cq;
        float b0v = bo[col], b1v = bo[col+1];
        *(float2*)&out[(size_t)r0*CC + col] =
            make_float2(acc[nb][0] + b0v, acc[nb][1] + b1v);
        *(float2*)&out[(size_t)r1*CC + col] =
            make_float2(acc[nb][2] + b0v, acc[nb][3] + b1v);
    }
}

// ---------------------------------------------------------------------------
extern "C" void kernel_launch(void* const* d_in, const int* in_sizes, int n_in,
                              void* d_out, int out_size)
{
    const float* x    = (const float*)d_in[0];
    const float* edge = (const float*)d_in[1];
    const float* Wq   = (const float*)d_in[2];
    const float* Wk   = (const float*)d_in[3];
    const float* Wv   = (const float*)d_in[4];
    const float* Wo   = (const float*)d_in[5];
    const float* bo   = (const float*)d_in[6];
    float* out = (float*)d_out;

    qkv_mma_kernel<<<dim3(15, 64), 256>>>(x, Wq, Wk, Wv, edge);
    vtrans_kernel<<<dim3(32, GG), 256>>>();

    cudaFuncSetAttribute(attn_mma_kernel,
                         cudaFuncAttributeMaxDynamicSharedMemorySize, ATTN_SMEM);
    attn_mma_kernel<<<dim3(16, GG), 256, ATTN_SMEM>>>();

    oproj_mma_kernel<<<dim3(5, 64), 256>>>(Wo, bo, out);
}

// round 13
// speedup vs baseline: 2.0988x; 1.4952x over previous
#include <cuda_runtime.h>
#include <cuda_bf16.h>
#include <cuda_fp16.h>
#include <cstdint>

#define BB 4
#define NN 2048
#define CC 320
#define HH 5
#define DD 64
#define GG (BB*HH)      // 20
#define ROWS (BB*NN)    // 8192

// scratch (allocation-free rule: __device__ globals)
__device__ __half        g_qf[GG*NN*DD];   // folded 0.125*e_i, fp16 single
__device__ __half        g_kf[GG*NN*DD];   // folded e_j, fp16 single
__device__ float         g_v [GG*NN*DD];   // fp32 (pre-transpose)
__device__ __half        g_vf[GG*DD*NN];   // transposed (g,d,n), fp16 single
__device__ __nv_bfloat16 g_oh[ROWS*CC];    // attn out, merged (b*N+n, h*64+d), hi
__device__ __nv_bfloat16 g_ol[ROWS*CC];    // lo

// ============================ helpers ======================================
__device__ __forceinline__ void mma_bf16(float* d,
    uint32_t a0, uint32_t a1, uint32_t a2, uint32_t a3,
    uint32_t b0, uint32_t b1)
{
    asm volatile(
        "mma.sync.aligned.m16n8k16.row.col.f32.bf16.bf16.f32 "
        "{%0,%1,%2,%3}, {%4,%5,%6,%7}, {%8,%9}, {%0,%1,%2,%3};"
        : "+f"(d[0]), "+f"(d[1]), "+f"(d[2]), "+f"(d[3])
        : "r"(a0), "r"(a1), "r"(a2), "r"(a3), "r"(b0), "r"(b1));
}

__device__ __forceinline__ void mma_fp16(float* d,
    uint32_t a0, uint32_t a1, uint32_t a2, uint32_t a3,
    uint32_t b0, uint32_t b1)
{
    asm volatile(
        "mma.sync.aligned.m16n8k16.row.col.f32.f16.f16.f32 "
        "{%0,%1,%2,%3}, {%4,%5,%6,%7}, {%8,%9}, {%0,%1,%2,%3};"
        : "+f"(d[0]), "+f"(d[1]), "+f"(d[2]), "+f"(d[3])
        : "r"(a0), "r"(a1), "r"(a2), "r"(a3), "r"(b0), "r"(b1));
}

__device__ __forceinline__ void bf16_split(float v, __nv_bfloat16& h, __nv_bfloat16& l) {
    h = __float2bfloat16(v);
    l = __float2bfloat16(v - __bfloat162float(h));
}

__device__ __forceinline__ uint32_t pack_half2(float a, float b) {
    __half2 t = __floats2half2_rn(a, b);     // x=a (low), y=b (high)
    return *(uint32_t*)&t;
}

__device__ __forceinline__ uint32_t smem_u32(const void* p) {
    uint32_t a;
    asm("{ .reg .u64 t; cvta.to.shared.u64 t, %1; cvt.u32.u64 %0, t; }"
        : "=r"(a) : "l"(p));
    return a;
}

__device__ __forceinline__ void cp16(uint32_t dst, const void* src) {
    asm volatile("cp.async.cg.shared.global [%0], [%1], 16;"
                 :: "r"(dst), "l"(src) : "memory");
}
#define CP_COMMIT() asm volatile("cp.async.commit_group;" ::: "memory")
#define CP_WAIT0()  asm volatile("cp.async.wait_group 0;" ::: "memory")
#define CP_WAIT1()  asm volatile("cp.async.wait_group 1;" ::: "memory")

// ---------------------------------------------------------------------------
// Kernel 1: QKV projection via bf16 hi/lo 3-chain MMA (verified).
// Epilogue now emits Q/K as SINGLE fp16 (folded), V as fp32.
// ---------------------------------------------------------------------------
#define X_STRIDE_W 20      // words per row (40 halves: 32 data + 8 pad)
__global__ void __launch_bounds__(256)
qkv_mma_kernel(const float* __restrict__ x,
               const float* __restrict__ Wq,
               const float* __restrict__ Wk,
               const float* __restrict__ Wv,
               const float* __restrict__ edge)
{
    __shared__ uint32_t smq[128*X_STRIDE_W*2 + 64*X_STRIDE_W*2];
    uint32_t* XhW = smq;
    uint32_t* XlW = XhW + 128*X_STRIDE_W;
    uint32_t* WhW = XlW + 128*X_STRIDE_W;
    uint32_t* WlW = WhW + 64*X_STRIDE_W;
    __nv_bfloat16* Xh = (__nv_bfloat16*)XhW;
    __nv_bfloat16* Xl = (__nv_bfloat16*)XlW;
    __nv_bfloat16* Wh = (__nv_bfloat16*)WhW;
    __nv_bfloat16* Wl = (__nv_bfloat16*)WlW;

    const int tid  = threadIdx.x;
    const int wid  = tid >> 5;
    const int lane = tid & 31;
    const int lq   = lane >> 2;
    const int cq   = lane & 3;
    const int rb   = wid * 16;
    const int colt = blockIdx.x;       // 0..14
    const int ot   = colt / 5;         // 0=q 1=k 2=v
    const int h    = colt % 5;
    const int wc0  = h * 64;
    const int row0 = blockIdx.y * 128;
    const float* __restrict__ W = (ot == 0) ? Wq : (ot == 1) ? Wk : Wv;

    float acc[8][4] = {};

    for (int k0 = 0; k0 < CC; k0 += 32) {
        __syncthreads();
        #pragma unroll
        for (int i = 0; i < 16; i++) {
            int e = tid + 256*i;
            int kk = e & 31, r = e >> 5;
            float v = x[(row0 + r)*CC + k0 + kk];
            __nv_bfloat16 hh, ll; bf16_split(v, hh, ll);
            Xh[r*40 + kk] = hh;
            Xl[r*40 + kk] = ll;
        }
        #pragma unroll
        for (int i = 0; i < 8; i++) {
            int e = tid + 256*i;
            int n = e & 63, kk = e >> 6;
            float v = W[(k0 + kk)*CC + wc0 + n];
            __nv_bfloat16 hh, ll; bf16_split(v, hh, ll);
            Wh[n*40 + kk] = hh;
            Wl[n*40 + kk] = ll;
        }
        __syncthreads();

        #pragma unroll
        for (int kc = 0; kc < 2; kc++) {
            const int wi = kc*8 + cq;
            uint32_t ah0 = XhW[(rb + lq    )*X_STRIDE_W + wi];
            uint32_t ah1 = XhW[(rb + lq + 8)*X_STRIDE_W + wi];
            uint32_t ah2 = XhW[(rb + lq    )*X_STRIDE_W + wi + 4];
            uint32_t ah3 = XhW[(rb + lq + 8)*X_STRIDE_W + wi + 4];
            uint32_t al0 = XlW[(rb + lq    )*X_STRIDE_W + wi];
            uint32_t al1 = XlW[(rb + lq + 8)*X_STRIDE_W + wi];
            uint32_t al2 = XlW[(rb + lq    )*X_STRIDE_W + wi + 4];
            uint32_t al3 = XlW[(rb + lq + 8)*X_STRIDE_W + wi + 4];
            #pragma unroll
            for (int nb = 0; nb < 8; nb++) {
                uint32_t bh0 = WhW[(nb*8 + lq)*X_STRIDE_W + wi];
                uint32_t bh1 = WhW[(nb*8 + lq)*X_STRIDE_W + wi + 4];
                uint32_t bl0 = WlW[(nb*8 + lq)*X_STRIDE_W + wi];
                uint32_t bl1 = WlW[(nb*8 + lq)*X_STRIDE_W + wi + 4];
                mma_bf16(acc[nb], ah0, ah1, ah2, ah3, bh0, bh1);
                mma_bf16(acc[nb], ah0, ah1, ah2, ah3, bl0, bl1);
                mma_bf16(acc[nb], al0, al1, al2, al3, bh0, bh1);
            }
        }
    }

    // ---- epilogue ----
    const int r0 = row0 + rb + lq;
    const int b  = r0 >> 11;
    const int n0 = r0 & 2047;
    const int n1 = n0 + 8;
    const int g  = b*HH + h;
    const size_t base0 = ((size_t)g*NN + n0)*DD;
    const size_t base1 = ((size_t)g*NN + n1)*DD;

    if (ot == 2) {
        #pragma unroll
        for (int nb = 0; nb < 8; nb++) {
            int col = nb*8 + 2*cq;
            *(float2*)&g_v[base0 + col] = make_float2(acc[nb][0], acc[nb][1]);
            *(float2*)&g_v[base1 + col] = make_float2(acc[nb][2], acc[nb][3]);
        }
    } else {
        const int eb = g & 3;                        // g % B  (batch-minor!)
        const float s  = (ot == 0) ? 0.125f : 1.0f;
        const float f0 = edge[eb*NN + n0] * s;
        const float f1 = edge[eb*NN + n1] * s;
        __half* __restrict__ df = (ot == 0) ? g_qf : g_kf;
        #pragma unroll
        for (int nb = 0; nb < 8; nb++) {
            int col = nb*8 + 2*cq;
            __half2 t0 = __floats2half2_rn(acc[nb][0]*f0, acc[nb][1]*f0);
            __half2 t1 = __floats2half2_rn(acc[nb][2]*f1, acc[nb][3]*f1);
            *(__half2*)&df[base0 + col] = t0;
            *(__half2*)&df[base1 + col] = t1;
        }
    }
}

// ---------------------------------------------------------------------------
// Kernel 1b: V transpose + fp16 convert: (g,n,d) f32 -> (g,d,n) fp16 single.
// ---------------------------------------------------------------------------
__global__ void __launch_bounds__(256)
vtrans_kernel()
{
    __shared__ float T[64][65];
    const int tid = threadIdx.x;
    const int nt  = blockIdx.x;      // n-tile of 64
    const int g   = blockIdx.y;

    #pragma unroll
    for (int i = 0; i < 16; i++) {
        int e = tid + 256*i;
        int d = e & 63, n = e >> 6;
        T[n][d] = g_v[((size_t)g*NN + nt*64 + n)*DD + d];
    }
    __syncthreads();
    #pragma unroll
    for (int i = 0; i < 8; i++) {
        int e = tid + 256*i;
        int np = e & 31, d = e >> 5;
        int n = 2*np;
        __half2 t = __floats2half2_rn(T[n][d], T[n+1][d]);
        size_t o = ((size_t)g*DD + d)*NN + nt*64 + n;
        *(__half2*)&g_vf[o] = t;
    }
}

// ---------------------------------------------------------------------------
// Kernel 2: flash attention, fp16 scheme:
//   S = Q K^T single-chain fp16  (logit err ~5e-5 absolute)
//   O += Ph V + Pl V  (P fp16 hi/lo, V fp16 single; err ~2.8e-4)
// K/V double-buffered via cp.async groups; manual-LDS fragment loads.
// Epilogue writes O as bf16 hi/lo into merged (b*N+n, h*64+d) layout.
// ---------------------------------------------------------------------------
#define QK_STRIDE_W 36          // words per row (144 B: 128 data + 16 pad)
#define V_STRIDE_W  68          // words per row (272 B: 256 data + 16 pad)
#define Q_B   0
#define K0_B  18432
#define K1_B  36864
#define V0_B  55296
#define V1_B  72704
#define ATTN_SMEM 90112

__global__ void __launch_bounds__(256, 2)
attn_mma_kernel()
{
    extern __shared__ char smx[];
    const uint32_t sb = smem_u32(smx);
    uint32_t* QW = (uint32_t*)(smx + Q_B);

    const int tid  = threadIdx.x;
    const int w    = tid >> 5;
    const int lane = tid & 31;
    const int lq   = lane >> 2;
    const int cq   = lane & 3;
    const int g    = blockIdx.y;
    const int i0   = blockIdx.x * 128;
    const int rb   = w * 16;

    // per-thread load indices
    const int qr = tid >> 1, qc = tid & 1;            // unused pattern helpers
    (void)qr; (void)qc;

    // ---- prologue: Q tile (group 0) ----
    #pragma unroll
    for (int i = 0; i < 4; i++) {
        int c = tid + 256*i;                 // 1024 chunks
        int r = c >> 3, cc = c & 7;
        cp16(sb + Q_B + r*144 + cc*16, g_qf + ((size_t)g*NN + i0 + r)*DD + cc*8);
    }
    CP_COMMIT();

    // ---- prologue: K/V stage 0 (group 1) ----
    #pragma unroll
    for (int i = 0; i < 4; i++) {
        int c = tid + 256*i;
        int j = c >> 3, cc = c & 7;
        cp16(sb + K0_B + j*144 + cc*16, g_kf + ((size_t)g*NN + j)*DD + cc*8);
    }
    #pragma unroll
    for (int i = 0; i < 4; i++) {
        int c = tid + 256*i;
        int d = c >> 4, cc = c & 15;
        cp16(sb + V0_B + d*272 + cc*16, g_vf + ((size_t)g*DD + d)*NN + cc*8);
    }
    CP_COMMIT();

    float Oacc[8][4] = {};
    float lsum0 = 0.0f, lsum1 = 0.0f;

    for (int jt = 0; jt < 16; jt++) {
        const int buf = jt & 1;

        // ---- prefetch next stage ----
        if (jt + 1 < 16) {
            const int j0n = (jt + 1) * 128;
            const uint32_t kb = (buf ? K0_B : K1_B);
            const uint32_t vb = (buf ? V0_B : V1_B);
            #pragma unroll
            for (int i = 0; i < 4; i++) {
                int c = tid + 256*i;
                int j = c >> 3, cc = c & 7;
                cp16(sb + kb + j*144 + cc*16,
                     g_kf + ((size_t)g*NN + j0n + j)*DD + cc*8);
            }
            #pragma unroll
            for (int i = 0; i < 4; i++) {
                int c = tid + 256*i;
                int d = c >> 4, cc = c & 15;
                cp16(sb + vb + d*272 + cc*16,
                     g_vf + ((size_t)g*DD + d)*NN + j0n + cc*8);
            }
            CP_COMMIT();
            CP_WAIT1();     // current stage complete; prefetch may be pending
        } else {
            CP_WAIT0();
        }
        __syncthreads();

        uint32_t* KW = (uint32_t*)(smx + (buf ? K1_B : K0_B));
        uint32_t* VW = (uint32_t*)(smx + (buf ? V1_B : V0_B));

        // ---- S = Q K^T : single-chain fp16 ----
        float S[16][4];
        #pragma unroll
        for (int nb = 0; nb < 16; nb++)
            #pragma unroll
            for (int i = 0; i < 4; i++) S[nb][i] = 0.0f;

        #pragma unroll
        for (int kc = 0; kc < 4; kc++) {
            const int wi = kc*8 + cq;
            uint32_t a0 = QW[(rb + lq    )*QK_STRIDE_W + wi];
            uint32_t a1 = QW[(rb + lq + 8)*QK_STRIDE_W + wi];
            uint32_t a2 = QW[(rb + lq    )*QK_STRIDE_W + wi + 4];
            uint32_t a3 = QW[(rb + lq + 8)*QK_STRIDE_W + wi + 4];
            #pragma unroll
            for (int nb = 0; nb < 16; nb++) {
                uint32_t b0 = KW[(nb*8 + lq)*QK_STRIDE_W + wi];
                uint32_t b1 = KW[(nb*8 + lq)*QK_STRIDE_W + wi + 4];
                mma_fp16(S[nb], a0, a1, a2, a3, b0, b1);
            }
        }

        // ---- softmax (logits bounded, no max needed) ----
        #pragma unroll
        for (int nb = 0; nb < 16; nb++) {
            float p0 = __expf(S[nb][0]);
            float p1 = __expf(S[nb][1]);
            float p2 = __expf(S[nb][2]);
            float p3 = __expf(S[nb][3]);
            S[nb][0] = p0; S[nb][1] = p1; S[nb][2] = p2; S[nb][3] = p3;
            lsum0 += p0 + p1;
            lsum1 += p2 + p3;
        }

        // ---- O += P V : P fp16 hi/lo (2 chains), V single fp16 ----
        #pragma unroll
        for (int kc = 0; kc < 8; kc++) {
            float p00 = S[2*kc][0],   p01 = S[2*kc][1];
            float p02 = S[2*kc][2],   p03 = S[2*kc][3];
            float p10 = S[2*kc+1][0], p11 = S[2*kc+1][1];
            float p12 = S[2*kc+1][2], p13 = S[2*kc+1][3];
            uint32_t ah0 = pack_half2(p00, p01);
            uint32_t ah1 = pack_half2(p02, p03);
            uint32_t ah2 = pack_half2(p10, p11);
            uint32_t ah3 = pack_half2(p12, p13);
            __half2 h0 = *(__half2*)&ah0;
            __half2 h1 = *(__half2*)&ah1;
            __half2 h2 = *(__half2*)&ah2;
            __half2 h3 = *(__half2*)&ah3;
            uint32_t al0 = pack_half2(p00 - __half2float(h0.x),
                                      p01 - __half2float(h0.y));
            uint32_t al1 = pack_half2(p02 - __half2float(h1.x),
                                      p03 - __half2float(h1.y));
            uint32_t al2 = pack_half2(p10 - __half2float(h2.x),
                                      p11 - __half2float(h2.y));
            uint32_t al3 = pack_half2(p12 - __half2float(h3.x),
                                      p13 - __half2float(h3.y));
            const int wi = kc*8 + cq;
            #pragma unroll
            for (int nd = 0; nd < 8; nd++) {
                uint32_t b0 = VW[(nd*8 + lq)*V_STRIDE_W + wi];
                uint32_t b1 = VW[(nd*8 + lq)*V_STRIDE_W + wi + 4];
                mma_fp16(Oacc[nd], ah0, ah1, ah2, ah3, b0, b1);
                mma_fp16(Oacc[nd], al0, al1, al2, al3, b0, b1);
            }
        }
        __syncthreads();   // all warps done with this stage before it is refilled
    }

    // ---- reduce row sums across the quad sharing each row ----
    lsum0 += __shfl_xor_sync(0xFFFFFFFF, lsum0, 1);
    lsum0 += __shfl_xor_sync(0xFFFFFFFF, lsum0, 2);
    lsum1 += __shfl_xor_sync(0xFFFFFFFF, lsum1, 1);
    lsum1 += __shfl_xor_sync(0xFFFFFFFF, lsum1, 2);
    const float inv0 = 1.0f / lsum0;
    const float inv1 = 1.0f / lsum1;

    // ---- write O as bf16 hi/lo into merged layout (row, h*64+d) ----
    const int b = g / HH, h = g % HH;
    const int rowg0 = b*NN + i0 + rb + lq;
    const int rowg1 = rowg0 + 8;
    #pragma unroll
    for (int nd = 0; nd < 8; nd++) {
        int col = h*64 + nd*8 + 2*cq;
        float v00 = Oacc[nd][0]*inv0, v01 = Oacc[nd][1]*inv0;
        float v10 = Oacc[nd][2]*inv1, v11 = Oacc[nd][3]*inv1;
        __nv_bfloat16 h00, l00, h01, l01, h10, l10, h11, l11;
        bf16_split(v00, h00, l00); bf16_split(v01, h01, l01);
        bf16_split(v10, h10, l10); bf16_split(v11, h11, l11);
        __nv_bfloat162 t;
        t.x = h00; t.y = h01; *(__nv_bfloat162*)&g_oh[(size_t)rowg0*CC + col] = t;
        t.x = l00; t.y = l01; *(__nv_bfloat162*)&g_ol[(size_t)rowg0*CC + col] = t;
        t.x = h10; t.y = h11; *(__nv_bfloat162*)&g_oh[(size_t)rowg1*CC + col] = t;
        t.x = l10; t.y = l11; *(__nv_bfloat162*)&g_ol[(size_t)rowg1*CC + col] = t;
    }
}

// ---------------------------------------------------------------------------
// Kernel 3: output projection via bf16 hi/lo 3-chain MMA + bias (verified).
// ---------------------------------------------------------------------------
__global__ void __launch_bounds__(256)
oproj_mma_kernel(const float* __restrict__ Wo,
                 const float* __restrict__ bo,
                 float* __restrict__ out)
{
    __shared__ uint32_t smq[128*X_STRIDE_W*2 + 64*X_STRIDE_W*2];
    const uint32_t sb = smem_u32(smq);
    uint32_t* XhW = smq;
    uint32_t* XlW = XhW + 128*X_STRIDE_W;
    uint32_t* WhW = XlW + 128*X_STRIDE_W;
    uint32_t* WlW = WhW + 64*X_STRIDE_W;
    __nv_bfloat16* Wh = (__nv_bfloat16*)WhW;
    __nv_bfloat16* Wl = (__nv_bfloat16*)WlW;
    const uint32_t XH_OFF = 0;
    const uint32_t XL_OFF = 128*X_STRIDE_W*4;

    const int tid  = threadIdx.x;
    const int wid  = tid >> 5;
    const int lane = tid & 31;
    const int lq   = lane >> 2;
    const int cq   = lane & 3;
    const int rb   = wid * 16;
    const int c0   = blockIdx.x * 64;
    const int row0 = blockIdx.y * 128;

    float acc[8][4] = {};

    for (int k0 = 0; k0 < CC; k0 += 32) {
        __syncthreads();
        // A tile via cp.async: 128 rows x 32 halves (64B) per buffer
        #pragma unroll
        for (int i = 0; i < 2; i++) {
            int c = tid + 256*i;
            int r = c >> 2, cc = c & 3;
            cp16(sb + XH_OFF + r*80 + cc*16, g_oh + (size_t)(row0 + r)*CC + k0 + cc*8);
            cp16(sb + XL_OFF + r*80 + cc*16, g_ol + (size_t)(row0 + r)*CC + k0 + cc*8);
        }
        // W tile: split fp32 -> hi/lo, stored [n][kk]
        #pragma unroll
        for (int i = 0; i < 8; i++) {
            int e = tid + 256*i;
            int n = e & 63, kk = e >> 6;
            float v = Wo[(k0 + kk)*CC + c0 + n];
            __nv_bfloat16 hh, ll; bf16_split(v, hh, ll);
            Wh[n*40 + kk] = hh;
            Wl[n*40 + kk] = ll;
        }
        CP_COMMIT();
        CP_WAIT0();
        __syncthreads();

        #pragma unroll
        for (int kc = 0; kc < 2; kc++) {
            const int wi = kc*8 + cq;
            uint32_t ah0 = XhW[(rb + lq    )*X_STRIDE_W + wi];
            uint32_t ah1 = XhW[(rb + lq + 8)*X_STRIDE_W + wi];
            uint32_t ah2 = XhW[(rb + lq    )*X_STRIDE_W + wi + 4];
            uint32_t ah3 = XhW[(rb + lq + 8)*X_STRIDE_W + wi + 4];
            uint32_t al0 = XlW[(rb + lq    )*X_STRIDE_W + wi];
            uint32_t al1 = XlW[(rb + lq + 8)*X_STRIDE_W + wi];
            uint32_t al2 = XlW[(rb + lq    )*X_STRIDE_W + wi + 4];
            uint32_t al3 = XlW[(rb + lq + 8)*X_STRIDE_W + wi + 4];
            #pragma unroll
            for (int nb = 0; nb < 8; nb++) {
                uint32_t bh0 = WhW[(nb*8 + lq)*X_STRIDE_W + wi];
                uint32_t bh1 = WhW[(nb*8 + lq)*X_STRIDE_W + wi + 4];
                uint32_t bl0 = WlW[(nb*8 + lq)*X_STRIDE_W + wi];
                uint32_t bl1 = WlW[(nb*8 + lq)*X_STRIDE_W + wi + 4];
                mma_bf16(acc[nb], ah0, ah1, ah2, ah3, bh0, bh1);
                mma_bf16(acc[nb], ah0, ah1, ah2, ah3, bl0, bl1);
                mma_bf16(acc[nb], al0, al1, al2, al3, bh0, bh1);
            }
        }
    }

    // ---- epilogue: add bias, write fp32 out ----
    const int r0 = row0 + rb + lq;
    const int r1 = r0 + 8;
    #pragma unroll
    for (int nb = 0; nb < 8; nb++) {
        int col = c0 + nb*8 + 2*cq;
        float b0v = bo[col], b1v = bo[col+1];
        *(float2*)&out[(size_t)r0*CC + col] =
            make_float2(acc[nb][0] + b0v, acc[nb][1] + b1v);
        *(float2*)&out[(size_t)r1*CC + col] =
            make_float2(acc[nb][2] + b0v, acc[nb][3] + b1v);
    }
}

// ---------------------------------------------------------------------------
extern "C" void kernel_launch(void* const* d_in, const int* in_sizes, int n_in,
                              void* d_out, int out_size)
{
    const float* x    = (const float*)d_in[0];
    const float* edge = (const float*)d_in[1];
    const float* Wq   = (const float*)d_in[2];
    const float* Wk   = (const float*)d_in[3];
    const float* Wv   = (const float*)d_in[4];
    const float* Wo   = (const float*)d_in[5];
    const float* bo   = (const float*)d_in[6];
    float* out = (float*)d_out;

    qkv_mma_kernel<<<dim3(15, 64), 256>>>(x, Wq, Wk, Wv, edge);
    vtrans_kernel<<<dim3(32, GG), 256>>>();

    cudaFuncSetAttribute(attn_mma_kernel,
                         cudaFuncAttributeMaxDynamicSharedMemorySize, ATTN_SMEM);
    attn_mma_kernel<<<dim3(16, GG), 256, ATTN_SMEM>>>();

    oproj_mma_kernel<<<dim3(5, 64), 256>>>(Wo, bo, out);
}

// round 14
// speedup vs baseline: 2.5386x; 1.2095x over previous
#include <cuda_runtime.h>
#include <cuda_bf16.h>
#include <cuda_fp16.h>
#include <cstdint>

#define BB 4
#define NN 2048
#define CC 320
#define HH 5
#define DD 64
#define GG (BB*HH)      // 20
#define ROWS (BB*NN)    // 8192

// scratch (allocation-free rule: __device__ globals)
__device__ __half        g_qf[GG*NN*DD];   // folded 0.125*e_i, fp16 single
__device__ __half        g_kf[GG*NN*DD];   // folded e_j, fp16 single
__device__ float         g_v [GG*NN*DD];   // fp32 (pre-transpose)
__device__ __half        g_vf[GG*DD*NN];   // transposed (g,d,n), fp16 single
__device__ __nv_bfloat16 g_oh[ROWS*CC];    // attn out, merged (b*N+n, h*64+d), hi
__device__ __nv_bfloat16 g_ol[ROWS*CC];    // lo

// ============================ helpers ======================================
__device__ __forceinline__ void mma_bf16(float* d,
    uint32_t a0, uint32_t a1, uint32_t a2, uint32_t a3,
    uint32_t b0, uint32_t b1)
{
    asm volatile(
        "mma.sync.aligned.m16n8k16.row.col.f32.bf16.bf16.f32 "
        "{%0,%1,%2,%3}, {%4,%5,%6,%7}, {%8,%9}, {%0,%1,%2,%3};"
        : "+f"(d[0]), "+f"(d[1]), "+f"(d[2]), "+f"(d[3])
        : "r"(a0), "r"(a1), "r"(a2), "r"(a3), "r"(b0), "r"(b1));
}

__device__ __forceinline__ void mma_fp16(float* d,
    uint32_t a0, uint32_t a1, uint32_t a2, uint32_t a3,
    uint32_t b0, uint32_t b1)
{
    asm volatile(
        "mma.sync.aligned.m16n8k16.row.col.f32.f16.f16.f32 "
        "{%0,%1,%2,%3}, {%4,%5,%6,%7}, {%8,%9}, {%0,%1,%2,%3};"
        : "+f"(d[0]), "+f"(d[1]), "+f"(d[2]), "+f"(d[3])
        : "r"(a0), "r"(a1), "r"(a2), "r"(a3), "r"(b0), "r"(b1));
}

__device__ __forceinline__ void bf16_split(float v, __nv_bfloat16& h, __nv_bfloat16& l) {
    h = __float2bfloat16(v);
    l = __float2bfloat16(v - __bfloat162float(h));
}

__device__ __forceinline__ uint32_t pack_half2(float a, float b) {
    __half2 t = __floats2half2_rn(a, b);     // x=a (low), y=b (high)
    return *(uint32_t*)&t;
}

__device__ __forceinline__ uint32_t smem_u32(const void* p) {
    uint32_t a;
    asm("{ .reg .u64 t; cvta.to.shared.u64 t, %1; cvt.u32.u64 %0, t; }"
        : "=r"(a) : "l"(p));
    return a;
}

__device__ __forceinline__ void cp16(uint32_t dst, const void* src) {
    asm volatile("cp.async.cg.shared.global [%0], [%1], 16;"
                 :: "r"(dst), "l"(src) : "memory");
}
#define CP_COMMIT() asm volatile("cp.async.commit_group;" ::: "memory")
#define CP_WAIT0()  asm volatile("cp.async.wait_group 0;" ::: "memory")
#define CP_WAIT1()  asm volatile("cp.async.wait_group 1;" ::: "memory")

// ---------------------------------------------------------------------------
// Kernel 1: QKV projection via bf16 hi/lo 3-chain MMA.
// NEW: cp.async staging pipeline — raw fp32 x/W tiles prefetched into smem
// during the previous iteration's MMA; hi/lo split becomes smem->smem.
// Epilogue emits Q/K as single fp16 (folded), V as fp32.
// ---------------------------------------------------------------------------
#define X_STRIDE_W 20      // words per row (40 halves: 32 data + 8 pad)
__global__ void __launch_bounds__(256)
qkv_mma_kernel(const float* __restrict__ x,
               const float* __restrict__ Wq,
               const float* __restrict__ Wk,
               const float* __restrict__ Wv,
               const float* __restrict__ edge)
{
    // bf16 buffers (30 KB) + fp32 staging (24 KB)
    __shared__ uint32_t smq[128*X_STRIDE_W*2 + 64*X_STRIDE_W*2];
    __shared__ float    Xs[128*32];      // staged x tile [r][kk]
    __shared__ float    Ws[32*64];       // staged W tile [kk][n]
    const uint32_t sbX = smem_u32(Xs);
    const uint32_t sbW = smem_u32(Ws);

    uint32_t* XhW = smq;
    uint32_t* XlW = XhW + 128*X_STRIDE_W;
    uint32_t* WhW = XlW + 128*X_STRIDE_W;
    uint32_t* WlW = WhW + 64*X_STRIDE_W;
    __nv_bfloat16* Xh = (__nv_bfloat16*)XhW;
    __nv_bfloat16* Xl = (__nv_bfloat16*)XlW;
    __nv_bfloat16* Wh = (__nv_bfloat16*)WhW;
    __nv_bfloat16* Wl = (__nv_bfloat16*)WlW;

    const int tid  = threadIdx.x;
    const int wid  = tid >> 5;
    const int lane = tid & 31;
    const int lq   = lane >> 2;
    const int cq   = lane & 3;
    const int rb   = wid * 16;
    const int colt = blockIdx.x;       // 0..14
    const int ot   = colt / 5;         // 0=q 1=k 2=v
    const int h    = colt % 5;
    const int wc0  = h * 64;
    const int row0 = blockIdx.y * 128;
    const float* __restrict__ W = (ot == 0) ? Wq : (ot == 1) ? Wk : Wv;

    // issue prefetch of first tile (k0 = 0)
    {
        #pragma unroll
        for (int i = 0; i < 4; i++) {            // X: 1024 16B chunks
            int c = tid + 256*i;
            int r = c >> 3, ch = c & 7;
            cp16(sbX + (uint32_t)(r*32 + ch*4)*4, &x[(row0 + r)*CC + ch*4]);
        }
        #pragma unroll
        for (int i = 0; i < 2; i++) {            // W: 512 16B chunks
            int c = tid + 256*i;
            int kk = c >> 4, ch = c & 15;
            cp16(sbW + (uint32_t)(kk*64 + ch*4)*4, &W[kk*CC + wc0 + ch*4]);
        }
        CP_COMMIT();
    }

    float acc[8][4] = {};

    for (int it = 0; it < 10; it++) {
        const int k0n = (it + 1) * 32;
        CP_WAIT0();
        __syncthreads();               // staging ready; prior MMA reads done

        // split staging -> bf16 hi/lo buffers (smem -> smem)
        #pragma unroll
        for (int i = 0; i < 16; i++) {
            int e = tid + 256*i;
            int kk = e & 31, r = e >> 5;
            float v = Xs[r*32 + kk];
            __nv_bfloat16 hh, ll; bf16_split(v, hh, ll);
            Xh[r*40 + kk] = hh;
            Xl[r*40 + kk] = ll;
        }
        #pragma unroll
        for (int i = 0; i < 8; i++) {
            int e = tid + 256*i;
            int n = e & 63, kk = e >> 6;
            float v = Ws[kk*64 + n];
            __nv_bfloat16 hh, ll; bf16_split(v, hh, ll);
            Wh[n*40 + kk] = hh;
            Wl[n*40 + kk] = ll;
        }
        __syncthreads();               // bf16 bufs ready; staging reads done

        // issue prefetch of next tile into staging (overlaps with MMA below)
        if (it + 1 < 10) {
            #pragma unroll
            for (int i = 0; i < 4; i++) {
                int c = tid + 256*i;
                int r = c >> 3, ch = c & 7;
                cp16(sbX + (uint32_t)(r*32 + ch*4)*4,
                     &x[(row0 + r)*CC + k0n + ch*4]);
            }
            #pragma unroll
            for (int i = 0; i < 2; i++) {
                int c = tid + 256*i;
                int kk = c >> 4, ch = c & 15;
                cp16(sbW + (uint32_t)(kk*64 + ch*4)*4,
                     &W[(k0n + kk)*CC + wc0 + ch*4]);
            }
            CP_COMMIT();
        }

        #pragma unroll
        for (int kc = 0; kc < 2; kc++) {
            const int wi = kc*8 + cq;
            uint32_t ah0 = XhW[(rb + lq    )*X_STRIDE_W + wi];
            uint32_t ah1 = XhW[(rb + lq + 8)*X_STRIDE_W + wi];
            uint32_t ah2 = XhW[(rb + lq    )*X_STRIDE_W + wi + 4];
            uint32_t ah3 = XhW[(rb + lq + 8)*X_STRIDE_W + wi + 4];
            uint32_t al0 = XlW[(rb + lq    )*X_STRIDE_W + wi];
            uint32_t al1 = XlW[(rb + lq + 8)*X_STRIDE_W + wi];
            uint32_t al2 = XlW[(rb + lq    )*X_STRIDE_W + wi + 4];
            uint32_t al3 = XlW[(rb + lq + 8)*X_STRIDE_W + wi + 4];
            #pragma unroll
            for (int nb = 0; nb < 8; nb++) {
                uint32_t bh0 = WhW[(nb*8 + lq)*X_STRIDE_W + wi];
                uint32_t bh1 = WhW[(nb*8 + lq)*X_STRIDE_W + wi + 4];
                uint32_t bl0 = WlW[(nb*8 + lq)*X_STRIDE_W + wi];
                uint32_t bl1 = WlW[(nb*8 + lq)*X_STRIDE_W + wi + 4];
                mma_bf16(acc[nb], ah0, ah1, ah2, ah3, bh0, bh1);
                mma_bf16(acc[nb], ah0, ah1, ah2, ah3, bl0, bl1);
                mma_bf16(acc[nb], al0, al1, al2, al3, bh0, bh1);
            }
        }
        __syncthreads();               // MMA reads done before next split
    }

    // ---- epilogue ----
    const int r0 = row0 + rb + lq;
    const int b  = r0 >> 11;
    const int n0 = r0 & 2047;
    const int n1 = n0 + 8;
    const int g  = b*HH + h;
    const size_t base0 = ((size_t)g*NN + n0)*DD;
    const size_t base1 = ((size_t)g*NN + n1)*DD;

    if (ot == 2) {
        #pragma unroll
        for (int nb = 0; nb < 8; nb++) {
            int col = nb*8 + 2*cq;
            *(float2*)&g_v[base0 + col] = make_float2(acc[nb][0], acc[nb][1]);
            *(float2*)&g_v[base1 + col] = make_float2(acc[nb][2], acc[nb][3]);
        }
    } else {
        const int eb = g & 3;                        // g % B  (batch-minor!)
        const float s  = (ot == 0) ? 0.125f : 1.0f;
        const float f0 = edge[eb*NN + n0] * s;
        const float f1 = edge[eb*NN + n1] * s;
        __half* __restrict__ df = (ot == 0) ? g_qf : g_kf;
        #pragma unroll
        for (int nb = 0; nb < 8; nb++) {
            int col = nb*8 + 2*cq;
            __half2 t0 = __floats2half2_rn(acc[nb][0]*f0, acc[nb][1]*f0);
            __half2 t1 = __floats2half2_rn(acc[nb][2]*f1, acc[nb][3]*f1);
            *(__half2*)&df[base0 + col] = t0;
            *(__half2*)&df[base1 + col] = t1;
        }
    }
}

// ---------------------------------------------------------------------------
// Kernel 1b: V transpose + fp16 convert: (g,n,d) f32 -> (g,d,n) fp16 single.
// ---------------------------------------------------------------------------
__global__ void __launch_bounds__(256)
vtrans_kernel()
{
    __shared__ float T[64][65];
    const int tid = threadIdx.x;
    const int nt  = blockIdx.x;      // n-tile of 64
    const int g   = blockIdx.y;

    #pragma unroll
    for (int i = 0; i < 16; i++) {
        int e = tid + 256*i;
        int d = e & 63, n = e >> 6;
        T[n][d] = g_v[((size_t)g*NN + nt*64 + n)*DD + d];
    }
    __syncthreads();
    #pragma unroll
    for (int i = 0; i < 8; i++) {
        int e = tid + 256*i;
        int np = e & 31, d = e >> 5;
        int n = 2*np;
        __half2 t = __floats2half2_rn(T[n][d], T[n+1][d]);
        size_t o = ((size_t)g*DD + d)*NN + nt*64 + n;
        *(__half2*)&g_vf[o] = t;
    }
}

// ---------------------------------------------------------------------------
// Kernel 2: flash attention, fp16 scheme:
//   S = Q K^T single-chain fp16  (logit err ~5e-5 absolute)
//   O += P V  (P single fp16, V single fp16)   <-- NEW: P_lo chain dropped
// K/V double-buffered via cp.async groups; manual-LDS fragment loads.
// Epilogue writes O as bf16 hi/lo into merged (b*N+n, h*64+d) layout.
// ---------------------------------------------------------------------------
#define QK_STRIDE_W 36          // words per row (144 B: 128 data + 16 pad)
#define V_STRIDE_W  68          // words per row (272 B: 256 data + 16 pad)
#define Q_B   0
#define K0_B  18432
#define K1_B  36864
#define V0_B  55296
#define V1_B  72704
#define ATTN_SMEM 90112

__global__ void __launch_bounds__(256, 2)
attn_mma_kernel()
{
    extern __shared__ char smx[];
    const uint32_t sb = smem_u32(smx);
    uint32_t* QW = (uint32_t*)(smx + Q_B);

    const int tid  = threadIdx.x;
    const int w    = tid >> 5;
    const int lane = tid & 31;
    const int lq   = lane >> 2;
    const int cq   = lane & 3;
    const int g    = blockIdx.y;
    const int i0   = blockIdx.x * 128;
    const int rb   = w * 16;

    // ---- prologue: Q tile (group 0) ----
    #pragma unroll
    for (int i = 0; i < 4; i++) {
        int c = tid + 256*i;                 // 1024 chunks
        int r = c >> 3, cc = c & 7;
        cp16(sb + Q_B + r*144 + cc*16, g_qf + ((size_t)g*NN + i0 + r)*DD + cc*8);
    }
    CP_COMMIT();

    // ---- prologue: K/V stage 0 (group 1) ----
    #pragma unroll
    for (int i = 0; i < 4; i++) {
        int c = tid + 256*i;
        int j = c >> 3, cc = c & 7;
        cp16(sb + K0_B + j*144 + cc*16, g_kf + ((size_t)g*NN + j)*DD + cc*8);
    }
    #pragma unroll
    for (int i = 0; i < 4; i++) {
        int c = tid + 256*i;
        int d = c >> 4, cc = c & 15;
        cp16(sb + V0_B + d*272 + cc*16, g_vf + ((size_t)g*DD + d)*NN + cc*8);
    }
    CP_COMMIT();

    float Oacc[8][4] = {};
    float lsum0 = 0.0f, lsum1 = 0.0f;

    for (int jt = 0; jt < 16; jt++) {
        const int buf = jt & 1;

        // ---- prefetch next stage ----
        if (jt + 1 < 16) {
            const int j0n = (jt + 1) * 128;
            const uint32_t kb = (buf ? K0_B : K1_B);
            const uint32_t vb = (buf ? V0_B : V1_B);
            #pragma unroll
            for (int i = 0; i < 4; i++) {
                int c = tid + 256*i;
                int j = c >> 3, cc = c & 7;
                cp16(sb + kb + j*144 + cc*16,
                     g_kf + ((size_t)g*NN + j0n + j)*DD + cc*8);
            }
            #pragma unroll
            for (int i = 0; i < 4; i++) {
                int c = tid + 256*i;
                int d = c >> 4, cc = c & 15;
                cp16(sb + vb + d*272 + cc*16,
                     g_vf + ((size_t)g*DD + d)*NN + j0n + cc*8);
            }
            CP_COMMIT();
            CP_WAIT1();     // current stage complete; prefetch may be pending
        } else {
            CP_WAIT0();
        }
        __syncthreads();

        uint32_t* KW = (uint32_t*)(smx + (buf ? K1_B : K0_B));
        uint32_t* VW = (uint32_t*)(smx + (buf ? V1_B : V0_B));

        // ---- S = Q K^T : single-chain fp16 ----
        float S[16][4];
        #pragma unroll
        for (int nb = 0; nb < 16; nb++)
            #pragma unroll
            for (int i = 0; i < 4; i++) S[nb][i] = 0.0f;

        #pragma unroll
        for (int kc = 0; kc < 4; kc++) {
            const int wi = kc*8 + cq;
            uint32_t a0 = QW[(rb + lq    )*QK_STRIDE_W + wi];
            uint32_t a1 = QW[(rb + lq + 8)*QK_STRIDE_W + wi];
            uint32_t a2 = QW[(rb + lq    )*QK_STRIDE_W + wi + 4];
            uint32_t a3 = QW[(rb + lq + 8)*QK_STRIDE_W + wi + 4];
            #pragma unroll
            for (int nb = 0; nb < 16; nb++) {
                uint32_t b0 = KW[(nb*8 + lq)*QK_STRIDE_W + wi];
                uint32_t b1 = KW[(nb*8 + lq)*QK_STRIDE_W + wi + 4];
                mma_fp16(S[nb], a0, a1, a2, a3, b0, b1);
            }
        }

        // ---- softmax (logits bounded, no max needed) ----
        #pragma unroll
        for (int nb = 0; nb < 16; nb++) {
            float p0 = __expf(S[nb][0]);
            float p1 = __expf(S[nb][1]);
            float p2 = __expf(S[nb][2]);
            float p3 = __expf(S[nb][3]);
            S[nb][0] = p0; S[nb][1] = p1; S[nb][2] = p2; S[nb][3] = p3;
            lsum0 += p0 + p1;
            lsum1 += p2 + p3;
        }

        // ---- O += P V : single-chain fp16 P, fp16 V ----
        #pragma unroll
        for (int kc = 0; kc < 8; kc++) {
            uint32_t a0 = pack_half2(S[2*kc][0],   S[2*kc][1]);
            uint32_t a1 = pack_half2(S[2*kc][2],   S[2*kc][3]);
            uint32_t a2 = pack_half2(S[2*kc+1][0], S[2*kc+1][1]);
            uint32_t a3 = pack_half2(S[2*kc+1][2], S[2*kc+1][3]);
            const int wi = kc*8 + cq;
            #pragma unroll
            for (int nd = 0; nd < 8; nd++) {
                uint32_t b0 = VW[(nd*8 + lq)*V_STRIDE_W + wi];
                uint32_t b1 = VW[(nd*8 + lq)*V_STRIDE_W + wi + 4];
                mma_fp16(Oacc[nd], a0, a1, a2, a3, b0, b1);
            }
        }
        __syncthreads();   // all warps done with this stage before it is refilled
    }

    // ---- reduce row sums across the quad sharing each row ----
    lsum0 += __shfl_xor_sync(0xFFFFFFFF, lsum0, 1);
    lsum0 += __shfl_xor_sync(0xFFFFFFFF, lsum0, 2);
    lsum1 += __shfl_xor_sync(0xFFFFFFFF, lsum1, 1);
    lsum1 += __shfl_xor_sync(0xFFFFFFFF, lsum1, 2);
    const float inv0 = 1.0f / lsum0;
    const float inv1 = 1.0f / lsum1;

    // ---- write O as bf16 hi/lo into merged layout (row, h*64+d) ----
    const int b = g / HH, h = g % HH;
    const int rowg0 = b*NN + i0 + rb + lq;
    const int rowg1 = rowg0 + 8;
    #pragma unroll
    for (int nd = 0; nd < 8; nd++) {
        int col = h*64 + nd*8 + 2*cq;
        float v00 = Oacc[nd][0]*inv0, v01 = Oacc[nd][1]*inv0;
        float v10 = Oacc[nd][2]*inv1, v11 = Oacc[nd][3]*inv1;
        __nv_bfloat16 h00, l00, h01, l01, h10, l10, h11, l11;
        bf16_split(v00, h00, l00); bf16_split(v01, h01, l01);
        bf16_split(v10, h10, l10); bf16_split(v11, h11, l11);
        __nv_bfloat162 t;
        t.x = h00; t.y = h01; *(__nv_bfloat162*)&g_oh[(size_t)rowg0*CC + col] = t;
        t.x = l00; t.y = l01; *(__nv_bfloat162*)&g_ol[(size_t)rowg0*CC + col] = t;
        t.x = h10; t.y = h11; *(__nv_bfloat162*)&g_oh[(size_t)rowg1*CC + col] = t;
        t.x = l10; t.y = l11; *(__nv_bfloat162*)&g_ol[(size_t)rowg1*CC + col] = t;
    }
}

// ---------------------------------------------------------------------------
// Kernel 3: output projection via bf16 hi/lo 3-chain MMA + bias (verified).
// ---------------------------------------------------------------------------
__global__ void __launch_bounds__(256)
oproj_mma_kernel(const float* __restrict__ Wo,
                 const float* __restrict__ bo,
                 float* __restrict__ out)
{
    __shared__ uint32_t smq[128*X_STRIDE_W*2 + 64*X_STRIDE_W*2];
    const uint32_t sb = smem_u32(smq);
    uint32_t* XhW = smq;
    uint32_t* XlW = XhW + 128*X_STRIDE_W;
    uint32_t* WhW = XlW + 128*X_STRIDE_W;
    uint32_t* WlW = WhW + 64*X_STRIDE_W;
    __nv_bfloat16* Wh = (__nv_bfloat16*)WhW;
    __nv_bfloat16* Wl = (__nv_bfloat16*)WlW;
    const uint32_t XH_OFF = 0;
    const uint32_t XL_OFF = 128*X_STRIDE_W*4;

    const int tid  = threadIdx.x;
    const int wid  = tid >> 5;
    const int lane = tid & 31;
    const int lq   = lane >> 2;
    const int cq   = lane & 3;
    const int rb   = wid * 16;
    const int c0   = blockIdx.x * 64;
    const int row0 = blockIdx.y * 128;

    float acc[8][4] = {};

    for (int k0 = 0; k0 < CC; k0 += 32) {
        __syncthreads();
        // A tile via cp.async: 128 rows x 32 halves (64B) per buffer
        #pragma unroll
        for (int i = 0; i < 2; i++) {
            int c = tid + 256*i;
            int r = c >> 2, cc = c & 3;
            cp16(sb + XH_OFF + r*80 + cc*16, g_oh + (size_t)(row0 + r)*CC + k0 + cc*8);
            cp16(sb + XL_OFF + r*80 + cc*16, g_ol + (size_t)(row0 + r)*CC + k0 + cc*8);
        }
        // W tile: split fp32 -> hi/lo, stored [n][kk]
        #pragma unroll
        for (int i = 0; i < 8; i++) {
            int e = tid + 256*i;
            int n = e & 63, kk = e >> 6;
            float v = Wo[(k0 + kk)*CC + c0 + n];
            __nv_bfloat16 hh, ll; bf16_split(v, hh, ll);
            Wh[n*40 + kk] = hh;
            Wl[n*40 + kk] = ll;
        }
        CP_COMMIT();
        CP_WAIT0();
        __syncthreads();

        #pragma unroll
        for (int kc = 0; kc < 2; kc++) {
            const int wi = kc*8 + cq;
            uint32_t ah0 = XhW[(rb + lq    )*X_STRIDE_W + wi];
            uint32_t ah1 = XhW[(rb + lq + 8)*X_STRIDE_W + wi];
            uint32_t ah2 = XhW[(rb + lq    )*X_STRIDE_W + wi + 4];
            uint32_t ah3 = XhW[(rb + lq + 8)*X_STRIDE_W + wi + 4];
            uint32_t al0 = XlW[(rb + lq    )*X_STRIDE_W + wi];
            uint32_t al1 = XlW[(rb + lq + 8)*X_STRIDE_W + wi];
            uint32_t al2 = XlW[(rb + lq    )*X_STRIDE_W + wi + 4];
            uint32_t al3 = XlW[(rb + lq + 8)*X_STRIDE_W + wi + 4];
            #pragma unroll
            for (int nb = 0; nb < 8; nb++) {
                uint32_t bh0 = WhW[(nb*8 + lq)*X_STRIDE_W + wi];
                uint32_t bh1 = WhW[(nb*8 + lq)*X_STRIDE_W + wi + 4];
                uint32_t bl0 = WlW[(nb*8 + lq)*X_STRIDE_W + wi];
                uint32_t bl1 = WlW[(nb*8 + lq)*X_STRIDE_W + wi + 4];
                mma_bf16(acc[nb], ah0, ah1, ah2, ah3, bh0, bh1);
                mma_bf16(acc[nb], ah0, ah1, ah2, ah3, bl0, bl1);
                mma_bf16(acc[nb], al0, al1, al2, al3, bh0, bh1);
            }
        }
    }

    // ---- epilogue: add bias, write fp32 out ----
    const int r0 = row0 + rb + lq;
    const int r1 = r0 + 8;
    #pragma unroll
    for (int nb = 0; nb < 8; nb++) {
        int col = c0 + nb*8 + 2*cq;
        float b0v = bo[col], b1v = bo[col+1];
        *(float2*)&out[(size_t)r0*CC + col] =
            make_float2(acc[nb][0] + b0v, acc[nb][1] + b1v);
        *(float2*)&out[(size_t)r1*CC + col] =
            make_float2(acc[nb][2] + b0v, acc[nb][3] + b1v);
    }
}

// ---------------------------------------------------------------------------
extern "C" void kernel_launch(void* const* d_in, const int* in_sizes, int n_in,
                              void* d_out, int out_size)
{
    const float* x    = (const float*)d_in[0];
    const float* edge = (const float*)d_in[1];
    const float* Wq   = (const float*)d_in[2];
    const float* Wk   = (const float*)d_in[3];
    const float* Wv   = (const float*)d_in[4];
    const float* Wo   = (const float*)d_in[5];
    const float* bo   = (const float*)d_in[6];
    float* out = (float*)d_out;

    qkv_mma_kernel<<<dim3(15, 64), 256>>>(x, Wq, Wk, Wv, edge);
    vtrans_kernel<<<dim3(32, GG), 256>>>();

    cudaFuncSetAttribute(attn_mma_kernel,
                         cudaFuncAttributeMaxDynamicSharedMemorySize, ATTN_SMEM);
    attn_mma_kernel<<<dim3(16, GG), 256, ATTN_SMEM>>>();

    oproj_mma_kernel<<<dim3(5, 64), 256>>>(Wo, bo, out);
}

// round 16
// speedup vs baseline: 2.5890x; 1.0199x over previous
#include <cuda_runtime.h>
#include <cuda_bf16.h>
#include <cuda_fp16.h>
#include <cstdint>

#define BB 4
#define NN 2048
#define CC 320
#define HH 5
#define DD 64
#define GG (BB*HH)      // 20
#define ROWS (BB*NN)    // 8192

// scratch (allocation-free rule: __device__ globals)
__device__ __half        g_qf[GG*NN*DD];   // folded 0.125*e_i, fp16 single
__device__ __half        g_kf[GG*NN*DD];   // folded e_j, fp16 single
__device__ __half        g_vf[GG*DD*NN];   // transposed (g,d,n), fp16 single
__device__ __nv_bfloat16 g_oh[ROWS*CC];    // attn out, merged (b*N+n, h*64+d), hi
__device__ __nv_bfloat16 g_ol[ROWS*CC];    // lo

// ============================ helpers ======================================
__device__ __forceinline__ void mma_bf16(float* d,
    uint32_t a0, uint32_t a1, uint32_t a2, uint32_t a3,
    uint32_t b0, uint32_t b1)
{
    asm volatile(
        "mma.sync.aligned.m16n8k16.row.col.f32.bf16.bf16.f32 "
        "{%0,%1,%2,%3}, {%4,%5,%6,%7}, {%8,%9}, {%0,%1,%2,%3};"
        : "+f"(d[0]), "+f"(d[1]), "+f"(d[2]), "+f"(d[3])
        : "r"(a0), "r"(a1), "r"(a2), "r"(a3), "r"(b0), "r"(b1));
}

__device__ __forceinline__ void mma_fp16(float* d,
    uint32_t a0, uint32_t a1, uint32_t a2, uint32_t a3,
    uint32_t b0, uint32_t b1)
{
    asm volatile(
        "mma.sync.aligned.m16n8k16.row.col.f32.f16.f16.f32 "
        "{%0,%1,%2,%3}, {%4,%5,%6,%7}, {%8,%9}, {%0,%1,%2,%3};"
        : "+f"(d[0]), "+f"(d[1]), "+f"(d[2]), "+f"(d[3])
        : "r"(a0), "r"(a1), "r"(a2), "r"(a3), "r"(b0), "r"(b1));
}

__device__ __forceinline__ void bf16_split(float v, __nv_bfloat16& h, __nv_bfloat16& l) {
    h = __float2bfloat16(v);
    l = __float2bfloat16(v - __bfloat162float(h));
}

__device__ __forceinline__ uint32_t pack_half2(float a, float b) {
    __half2 t = __floats2half2_rn(a, b);     // x=a (low), y=b (high)
    return *(uint32_t*)&t;
}

__device__ __forceinline__ uint32_t smem_u32(const void* p) {
    uint32_t a;
    asm("{ .reg .u64 t; cvta.to.shared.u64 t, %1; cvt.u32.u64 %0, t; }"
        : "=r"(a) : "l"(p));
    return a;
}

__device__ __forceinline__ void cp16(uint32_t dst, const void* src) {
    asm volatile("cp.async.cg.shared.global [%0], [%1], 16;"
                 :: "r"(dst), "l"(src) : "memory");
}
#define CP_COMMIT() asm volatile("cp.async.commit_group;" ::: "memory")
#define CP_WAIT0()  asm volatile("cp.async.wait_group 0;" ::: "memory")
#define CP_WAIT1()  asm volatile("cp.async.wait_group 1;" ::: "memory")

// ---------------------------------------------------------------------------
// Kernel 1: QKV projection via bf16 hi/lo 3-chain MMA + cp.async staging.
// V epilogue transposes in smem and writes g_vf (g,d,n) fp16 directly —
// vtrans kernel and the fp32 g_v round-trip are gone.
// ---------------------------------------------------------------------------
#define X_STRIDE_W 20      // words per row (40 halves: 32 data + 8 pad)
#define TS_STRIDE_H 136    // transpose buffer row stride in halves (272 B)
__global__ void __launch_bounds__(256)
qkv_mma_kernel(const float* __restrict__ x,
               const float* __restrict__ Wq,
               const float* __restrict__ Wk,
               const float* __restrict__ Wv,
               const float* __restrict__ edge)
{
    // bf16 buffers (30 KB) + fp32 staging (24 KB, reused as V-transpose buf)
    __shared__ uint32_t smq[128*X_STRIDE_W*2 + 64*X_STRIDE_W*2];
    __shared__ float    stage[6144];     // Xs = stage[0..4096), Ws = [4096..6144)
    float* Xs = stage;
    float* Ws = stage + 4096;
    const uint32_t sbX = smem_u32(Xs);
    const uint32_t sbW = smem_u32(Ws);

    uint32_t* XhW = smq;
    uint32_t* XlW = XhW + 128*X_STRIDE_W;
    uint32_t* WhW = XlW + 128*X_STRIDE_W;
    uint32_t* WlW = WhW + 64*X_STRIDE_W;
    __nv_bfloat16* Xh = (__nv_bfloat16*)XhW;
    __nv_bfloat16* Xl = (__nv_bfloat16*)XlW;
    __nv_bfloat16* Wh = (__nv_bfloat16*)WhW;
    __nv_bfloat16* Wl = (__nv_bfloat16*)WlW;

    const int tid  = threadIdx.x;
    const int wid  = tid >> 5;
    const int lane = tid & 31;
    const int lq   = lane >> 2;
    const int cq   = lane & 3;
    const int rb   = wid * 16;
    const int colt = blockIdx.x;       // 0..14
    const int ot   = colt / 5;         // 0=q 1=k 2=v
    const int h    = colt % 5;
    const int wc0  = h * 64;
    const int row0 = blockIdx.y * 128;
    const float* __restrict__ W = (ot == 0) ? Wq : (ot == 1) ? Wk : Wv;

    // issue prefetch of first tile (k0 = 0)
    {
        #pragma unroll
        for (int i = 0; i < 4; i++) {            // X: 1024 16B chunks
            int c = tid + 256*i;
            int r = c >> 3, ch = c & 7;
            cp16(sbX + (uint32_t)(r*32 + ch*4)*4, &x[(row0 + r)*CC + ch*4]);
        }
        #pragma unroll
        for (int i = 0; i < 2; i++) {            // W: 512 16B chunks
            int c = tid + 256*i;
            int kk = c >> 4, ch = c & 15;
            cp16(sbW + (uint32_t)(kk*64 + ch*4)*4, &W[kk*CC + wc0 + ch*4]);
        }
        CP_COMMIT();
    }

    float acc[8][4] = {};

    for (int it = 0; it < 10; it++) {
        const int k0n = (it + 1) * 32;
        CP_WAIT0();
        __syncthreads();               // staging ready; prior MMA reads done

        // split staging -> bf16 hi/lo buffers (smem -> smem)
        #pragma unroll
        for (int i = 0; i < 16; i++) {
            int e = tid + 256*i;
            int kk = e & 31, r = e >> 5;
            float v = Xs[r*32 + kk];
            __nv_bfloat16 hh, ll; bf16_split(v, hh, ll);
            Xh[r*40 + kk] = hh;
            Xl[r*40 + kk] = ll;
        }
        #pragma unroll
        for (int i = 0; i < 8; i++) {
            int e = tid + 256*i;
            int n = e & 63, kk = e >> 6;
            float v = Ws[kk*64 + n];
            __nv_bfloat16 hh, ll; bf16_split(v, hh, ll);
            Wh[n*40 + kk] = hh;
            Wl[n*40 + kk] = ll;
        }
        __syncthreads();               // bf16 bufs ready; staging reads done

        // issue prefetch of next tile into staging (overlaps with MMA below)
        if (it + 1 < 10) {
            #pragma unroll
            for (int i = 0; i < 4; i++) {
                int c = tid + 256*i;
                int r = c >> 3, ch = c & 7;
                cp16(sbX + (uint32_t)(r*32 + ch*4)*4,
                     &x[(row0 + r)*CC + k0n + ch*4]);
            }
            #pragma unroll
            for (int i = 0; i < 2; i++) {
                int c = tid + 256*i;
                int kk = c >> 4, ch = c & 15;
                cp16(sbW + (uint32_t)(kk*64 + ch*4)*4,
                     &W[(k0n + kk)*CC + wc0 + ch*4]);
            }
            CP_COMMIT();
        }

        #pragma unroll
        for (int kc = 0; kc < 2; kc++) {
            const int wi = kc*8 + cq;
            uint32_t ah0 = XhW[(rb + lq    )*X_STRIDE_W + wi];
            uint32_t ah1 = XhW[(rb + lq + 8)*X_STRIDE_W + wi];
            uint32_t ah2 = XhW[(rb + lq    )*X_STRIDE_W + wi + 4];
            uint32_t ah3 = XhW[(rb + lq + 8)*X_STRIDE_W + wi + 4];
            uint32_t al0 = XlW[(rb + lq    )*X_STRIDE_W + wi];
            uint32_t al1 = XlW[(rb + lq + 8)*X_STRIDE_W + wi];
            uint32_t al2 = XlW[(rb + lq    )*X_STRIDE_W + wi + 4];
            uint32_t al3 = XlW[(rb + lq + 8)*X_STRIDE_W + wi + 4];
            #pragma unroll
            for (int nb = 0; nb < 8; nb++) {
                uint32_t bh0 = WhW[(nb*8 + lq)*X_STRIDE_W + wi];
                uint32_t bh1 = WhW[(nb*8 + lq)*X_STRIDE_W + wi + 4];
                uint32_t bl0 = WlW[(nb*8 + lq)*X_STRIDE_W + wi];
                uint32_t bl1 = WlW[(nb*8 + lq)*X_STRIDE_W + wi + 4];
                mma_bf16(acc[nb], ah0, ah1, ah2, ah3, bh0, bh1);
                mma_bf16(acc[nb], ah0, ah1, ah2, ah3, bl0, bl1);
                mma_bf16(acc[nb], al0, al1, al2, al3, bh0, bh1);
            }
        }
        __syncthreads();               // MMA reads done before next split
    }

    // ---- epilogue ----
    const int r0 = row0 + rb + lq;
    const int b  = r0 >> 11;
    const int n0 = r0 & 2047;
    const int n1 = n0 + 8;
    const int g  = b*HH + h;

    if (ot == 2) {
        // V: transpose via smem (reuse staging area) and write g_vf (g,d,n) fp16.
        __half* Ts = (__half*)stage;           // 64 x 136 halves = 17408 B
        const int nl = rb + lq;                // local n within tile (0..127)
        #pragma unroll
        for (int nb = 0; nb < 8; nb++) {
            int col = nb*8 + 2*cq;             // d index
            Ts[ col     *TS_STRIDE_H + nl    ] = __float2half_rn(acc[nb][0]);
            Ts[(col + 1)*TS_STRIDE_H + nl    ] = __float2half_rn(acc[nb][1]);
            Ts[ col     *TS_STRIDE_H + nl + 8] = __float2half_rn(acc[nb][2]);
            Ts[(col + 1)*TS_STRIDE_H + nl + 8] = __float2half_rn(acc[nb][3]);
        }
        __syncthreads();
        // cooperative coalesced store: thread -> (d = tid>>2, n-chunk = tid&3)
        const int d  = tid >> 2;
        const int ch = tid & 3;
        const int n0t = row0 & 2047;           // tile base n (tile within one b)
        const uint4* src = (const uint4*)&Ts[d*TS_STRIDE_H + ch*32];
        uint4* dst = (uint4*)&g_vf[((size_t)g*DD + d)*NN + n0t + ch*32];
        #pragma unroll
        for (int i = 0; i < 4; i++) dst[i] = src[i];
    } else {
        const size_t base0 = ((size_t)g*NN + n0)*DD;
        const size_t base1 = ((size_t)g*NN + n1)*DD;
        const int eb = g & 3;                        // g % B  (batch-minor!)
        const float s  = (ot == 0) ? 0.125f : 1.0f;
        const float f0 = edge[eb*NN + n0] * s;
        const float f1 = edge[eb*NN + n1] * s;
        __half* __restrict__ df = (ot == 0) ? g_qf : g_kf;
        #pragma unroll
        for (int nb = 0; nb < 8; nb++) {
            int col = nb*8 + 2*cq;
            __half2 t0 = __floats2half2_rn(acc[nb][0]*f0, acc[nb][1]*f0);
            __half2 t1 = __floats2half2_rn(acc[nb][2]*f1, acc[nb][3]*f1);
            *(__half2*)&df[base0 + col] = t0;
            *(__half2*)&df[base1 + col] = t1;
        }
    }
}

// ---------------------------------------------------------------------------
// Kernel 2: flash attention, fp16 single-chain S and PV (verified R14).
// K/V double-buffered via cp.async groups; manual-LDS fragment loads.
// Epilogue writes O as bf16 hi/lo into merged (b*N+n, h*64+d) layout.
// ---------------------------------------------------------------------------
#define QK_STRIDE_W 36          // words per row (144 B: 128 data + 16 pad)
#define V_STRIDE_W  68          // words per row (272 B: 256 data + 16 pad)
#define Q_B   0
#define K0_B  18432
#define K1_B  36864
#define V0_B  55296
#define V1_B  72704
#define ATTN_SMEM 90112

__global__ void __launch_bounds__(256, 2)
attn_mma_kernel()
{
    extern __shared__ char smx[];
    const uint32_t sb = smem_u32(smx);
    uint32_t* QW = (uint32_t*)(smx + Q_B);

    const int tid  = threadIdx.x;
    const int w    = tid >> 5;
    const int lane = tid & 31;
    const int lq   = lane >> 2;
    const int cq   = lane & 3;
    const int g    = blockIdx.y;
    const int i0   = blockIdx.x * 128;
    const int rb   = w * 16;

    // ---- prologue: Q tile (group 0) ----
    #pragma unroll
    for (int i = 0; i < 4; i++) {
        int c = tid + 256*i;                 // 1024 chunks
        int r = c >> 3, cc = c & 7;
        cp16(sb + Q_B + r*144 + cc*16, g_qf + ((size_t)g*NN + i0 + r)*DD + cc*8);
    }
    CP_COMMIT();

    // ---- prologue: K/V stage 0 (group 1) ----
    #pragma unroll
    for (int i = 0; i < 4; i++) {
        int c = tid + 256*i;
        int j = c >> 3, cc = c & 7;
        cp16(sb + K0_B + j*144 + cc*16, g_kf + ((size_t)g*NN + j)*DD + cc*8);
    }
    #pragma unroll
    for (int i = 0; i < 4; i++) {
        int c = tid + 256*i;
        int d = c >> 4, cc = c & 15;
        cp16(sb + V0_B + d*272 + cc*16, g_vf + ((size_t)g*DD + d)*NN + cc*8);
    }
    CP_COMMIT();

    float Oacc[8][4] = {};
    float lsum0 = 0.0f, lsum1 = 0.0f;

    for (int jt = 0; jt < 16; jt++) {
        const int buf = jt & 1;

        // ---- prefetch next stage ----
        if (jt + 1 < 16) {
            const int j0n = (jt + 1) * 128;
            const uint32_t kb = (buf ? K0_B : K1_B);
            const uint32_t vb = (buf ? V0_B : V1_B);
            #pragma unroll
            for (int i = 0; i < 4; i++) {
                int c = tid + 256*i;
                int j = c >> 3, cc = c & 7;
                cp16(sb + kb + j*144 + cc*16,
                     g_kf + ((size_t)g*NN + j0n + j)*DD + cc*8);
            }
            #pragma unroll
            for (int i = 0; i < 4; i++) {
                int c = tid + 256*i;
                int d = c >> 4, cc = c & 15;
                cp16(sb + vb + d*272 + cc*16,
                     g_vf + ((size_t)g*DD + d)*NN + j0n + cc*8);
            }
            CP_COMMIT();
            CP_WAIT1();     // current stage complete; prefetch may be pending
        } else {
            CP_WAIT0();
        }
        __syncthreads();

        uint32_t* KW = (uint32_t*)(smx + (buf ? K1_B : K0_B));
        uint32_t* VW = (uint32_t*)(smx + (buf ? V1_B : V0_B));

        // ---- S = Q K^T : single-chain fp16 ----
        float S[16][4];
        #pragma unroll
        for (int nb = 0; nb < 16; nb++)
            #pragma unroll
            for (int i = 0; i < 4; i++) S[nb][i] = 0.0f;

        #pragma unroll
        for (int kc = 0; kc < 4; kc++) {
            const int wi = kc*8 + cq;
            uint32_t a0 = QW[(rb + lq    )*QK_STRIDE_W + wi];
            uint32_t a1 = QW[(rb + lq + 8)*QK_STRIDE_W + wi];
            uint32_t a2 = QW[(rb + lq    )*QK_STRIDE_W + wi + 4];
            uint32_t a3 = QW[(rb + lq + 8)*QK_STRIDE_W + wi + 4];
            #pragma unroll
            for (int nb = 0; nb < 16; nb++) {
                uint32_t b0 = KW[(nb*8 + lq)*QK_STRIDE_W + wi];
                uint32_t b1 = KW[(nb*8 + lq)*QK_STRIDE_W + wi + 4];
                mma_fp16(S[nb], a0, a1, a2, a3, b0, b1);
            }
        }

        // ---- softmax (logits bounded, no max needed) ----
        #pragma unroll
        for (int nb = 0; nb < 16; nb++) {
            float p0 = __expf(S[nb][0]);
            float p1 = __expf(S[nb][1]);
            float p2 = __expf(S[nb][2]);
            float p3 = __expf(S[nb][3]);
            S[nb][0] = p0; S[nb][1] = p1; S[nb][2] = p2; S[nb][3] = p3;
            lsum0 += p0 + p1;
            lsum1 += p2 + p3;
        }

        // ---- O += P V : single-chain fp16 P, fp16 V ----
        #pragma unroll
        for (int kc = 0; kc < 8; kc++) {
            uint32_t a0 = pack_half2(S[2*kc][0],   S[2*kc][1]);
            uint32_t a1 = pack_half2(S[2*kc][2],   S[2*kc][3]);
            uint32_t a2 = pack_half2(S[2*kc+1][0], S[2*kc+1][1]);
            uint32_t a3 = pack_half2(S[2*kc+1][2], S[2*kc+1][3]);
            const int wi = kc*8 + cq;
            #pragma unroll
            for (int nd = 0; nd < 8; nd++) {
                uint32_t b0 = VW[(nd*8 + lq)*V_STRIDE_W + wi];
                uint32_t b1 = VW[(nd*8 + lq)*V_STRIDE_W + wi + 4];
                mma_fp16(Oacc[nd], a0, a1, a2, a3, b0, b1);
            }
        }
        __syncthreads();   // all warps done with this stage before it is refilled
    }

    // ---- reduce row sums across the quad sharing each row ----
    lsum0 += __shfl_xor_sync(0xFFFFFFFF, lsum0, 1);
    lsum0 += __shfl_xor_sync(0xFFFFFFFF, lsum0, 2);
    lsum1 += __shfl_xor_sync(0xFFFFFFFF, lsum1, 1);
    lsum1 += __shfl_xor_sync(0xFFFFFFFF, lsum1, 2);
    const float inv0 = 1.0f / lsum0;
    const float inv1 = 1.0f / lsum1;

    // ---- write O as bf16 hi/lo into merged layout (row, h*64+d) ----
    const int b = g / HH, h = g % HH;
    const int rowg0 = b*NN + i0 + rb + lq;
    const int rowg1 = rowg0 + 8;
    #pragma unroll
    for (int nd = 0; nd < 8; nd++) {
        int col = h*64 + nd*8 + 2*cq;
        float v00 = Oacc[nd][0]*inv0, v01 = Oacc[nd][1]*inv0;
        float v10 = Oacc[nd][2]*inv1, v11 = Oacc[nd][3]*inv1;
        __nv_bfloat16 h00, l00, h01, l01, h10, l10, h11, l11;
        bf16_split(v00, h00, l00); bf16_split(v01, h01, l01);
        bf16_split(v10, h10, l10); bf16_split(v11, h11, l11);
        __nv_bfloat162 t;
        t.x = h00; t.y = h01; *(__nv_bfloat162*)&g_oh[(size_t)rowg0*CC + col] = t;
        t.x = l00; t.y = l01; *(__nv_bfloat162*)&g_ol[(size_t)rowg0*CC + col] = t;
        t.x = h10; t.y = h11; *(__nv_bfloat162*)&g_oh[(size_t)rowg1*CC + col] = t;
        t.x = l10; t.y = l11; *(__nv_bfloat162*)&g_ol[(size_t)rowg1*CC + col] = t;
    }
}

// ---------------------------------------------------------------------------
// Kernel 3: output projection, bf16 hi/lo 3-chain MMA + bias.
// Fully double-buffered (A ping-pong + Wo fp32 staging via cp.async,
// split smem->smem) — prefetch of k0+1 overlaps the MMA phase of k0.
// ---------------------------------------------------------------------------
// smem layout (words):
//  XH0 @ 0      (2560)   XL0 @ 2560   XH1 @ 5120   XL1 @ 7680
//  WhW @ 10240  (1280)   WlW @ 11520
//  Wst0 @ 12800 (2048)   Wst1 @ 14848        total 16896 words = 67584 B
__global__ void __launch_bounds__(256)
oproj_mma_kernel(const float* __restrict__ Wo,
                 const float* __restrict__ bo,
                 float* __restrict__ out)
{
    __shared__ uint32_t osm[16896];
    const uint32_t sb = smem_u32(osm);
    uint32_t* WhW = osm + 10240;
    uint32_t* WlW = osm + 11520;
    __nv_bfloat16* Wh = (__nv_bfloat16*)WhW;
    __nv_bfloat16* Wl = (__nv_bfloat16*)WlW;

    const int tid  = threadIdx.x;
    const int wid  = tid >> 5;
    const int lane = tid & 31;
    const int lq   = lane >> 2;
    const int cq   = lane & 3;
    const int rb   = wid * 16;
    const int c0   = blockIdx.x * 64;
    const int row0 = blockIdx.y * 128;

    // prologue: prefetch k0=0 into buffer 0
    {
        #pragma unroll
        for (int i = 0; i < 2; i++) {
            int c = tid + 256*i;
            int r = c >> 2, cc = c & 3;
            cp16(sb + (0    )*4 + r*80 + cc*16,
                 g_oh + (size_t)(row0 + r)*CC + cc*8);
            cp16(sb + (2560 )*4 + r*80 + cc*16,
                 g_ol + (size_t)(row0 + r)*CC + cc*8);
        }
        #pragma unroll
        for (int i = 0; i < 2; i++) {
            int c = tid + 256*i;
            int kk = c >> 4, ch = c & 15;
            cp16(sb + (12800)*4 + (uint32_t)(kk*64 + ch*4)*4,
                 &Wo[kk*CC + c0 + ch*4]);
        }
        CP_COMMIT();
    }

    float acc[8][4] = {};

    for (int it = 0; it < 10; it++) {
        const int buf = it & 1;
        const uint32_t xh_off = buf ? 5120u : 0u;
        const uint32_t xl_off = xh_off + 2560u;
        const uint32_t ws_off = buf ? 14848u : 12800u;

        CP_WAIT0();
        __syncthreads();               // current stage ready; prior MMA done

        // split Wo staging -> bf16 hi/lo [n][kk]
        {
            const float* Wst = (const float*)(osm + ws_off);
            #pragma unroll
            for (int i = 0; i < 8; i++) {
                int e = tid + 256*i;
                int n = e & 63, kk = e >> 6;
                float v = Wst[kk*64 + n];
                __nv_bfloat16 hh, ll; bf16_split(v, hh, ll);
                Wh[n*40 + kk] = hh;
                Wl[n*40 + kk] = ll;
            }
        }

        // prefetch next stage into alternate buffers (overlaps MMA)
        if (it + 1 < 10) {
            const int k0n = (it + 1) * 32;
            const uint32_t xh_n = buf ? 0u : 5120u;
            const uint32_t xl_n = xh_n + 2560u;
            const uint32_t ws_n = buf ? 12800u : 14848u;
            #pragma unroll
            for (int i = 0; i < 2; i++) {
                int c = tid + 256*i;
                int r = c >> 2, cc = c & 3;
                cp16(sb + xh_n*4 + r*80 + cc*16,
                     g_oh + (size_t)(row0 + r)*CC + k0n + cc*8);
                cp16(sb + xl_n*4 + r*80 + cc*16,
                     g_ol + (size_t)(row0 + r)*CC + k0n + cc*8);
            }
            #pragma unroll
            for (int i = 0; i < 2; i++) {
                int c = tid + 256*i;
                int kk = c >> 4, ch = c & 15;
                cp16(sb + ws_n*4 + (uint32_t)(kk*64 + ch*4)*4,
                     &Wo[(k0n + kk)*CC + c0 + ch*4]);
            }
            CP_COMMIT();
        }
        __syncthreads();               // Wh/Wl ready for all warps

        const uint32_t* XhW = osm + xh_off;
        const uint32_t* XlW = osm + xl_off;
        #pragma unroll
        for (int kc = 0; kc < 2; kc++) {
            const int wi = kc*8 + cq;
            uint32_t ah0 = XhW[(rb + lq    )*X_STRIDE_W + wi];
            uint32_t ah1 = XhW[(rb + lq + 8)*X_STRIDE_W + wi];
            uint32_t ah2 = XhW[(rb + lq    )*X_STRIDE_W + wi + 4];
            uint32_t ah3 = XhW[(rb + lq + 8)*X_STRIDE_W + wi + 4];
            uint32_t al0 = XlW[(rb + lq    )*X_STRIDE_W + wi];
            uint32_t al1 = XlW[(rb + lq + 8)*X_STRIDE_W + wi];
            uint32_t al2 = XlW[(rb + lq    )*X_STRIDE_W + wi + 4];
            uint32_t al3 = XlW[(rb + lq + 8)*X_STRIDE_W + wi + 4];
            #pragma unroll
            for (int nb = 0; nb < 8; nb++) {
                uint32_t bh0 = WhW[(nb*8 + lq)*X_STRIDE_W + wi];
                uint32_t bh1 = WhW[(nb*8 + lq)*X_STRIDE_W + wi + 4];
                uint32_t bl0 = WlW[(nb*8 + lq)*X_STRIDE_W + wi];
                uint32_t bl1 = WlW[(nb*8 + lq)*X_STRIDE_W + wi + 4];
                mma_bf16(acc[nb], ah0, ah1, ah2, ah3, bh0, bh1);
                mma_bf16(acc[nb], ah0, ah1, ah2, ah3, bl0, bl1);
                mma_bf16(acc[nb], al0, al1, al2, al3, bh0, bh1);
            }
        }
    }

    // ---- epilogue: add bias, write fp32 out ----
    const int r0 = row0 + rb + lq;
    const int r1 = r0 + 8;
    #pragma unroll
    for (int nb = 0; nb < 8; nb++) {
        int col = c0 + nb*8 + 2*cq;
        float b0v = bo[col], b1v = bo[col+1];
        *(float2*)&out[(size_t)r0*CC + col] =
            make_float2(acc[nb][0] + b0v, acc[nb][1] + b1v);
        *(float2*)&out[(size_t)r1*CC + col] =
            make_float2(acc[nb][2] + b0v, acc[nb][3] + b1v);
    }
}

// ---------------------------------------------------------------------------
extern "C" void kernel_launch(void* const* d_in, const int* in_sizes, int n_in,
                              void* d_out, int out_size)
{
    const float* x    = (const float*)d_in[0];
    const float* edge = (const float*)d_in[1];
    const float* Wq   = (const float*)d_in[2];
    const float* Wk   = (const float*)d_in[3];
    const float* Wv   = (const float*)d_in[4];
    const float* Wo   = (const float*)d_in[5];
    const float* bo   = (const float*)d_in[6];
    float* out = (float*)d_out;

    qkv_mma_kernel<<<dim3(15, 64), 256>>>(x, Wq, Wk, Wv, edge);

    cudaFuncSetAttribute(attn_mma_kernel,
                         cudaFuncAttributeMaxDynamicSharedMemorySize, ATTN_SMEM);
    attn_mma_kernel<<<dim3(16, GG), 256, ATTN_SMEM>>>();

    oproj_mma_kernel<<<dim3(5, 64), 256>>>(Wo, bo, out);
}

// round 17
// speedup vs baseline: 2.8828x; 1.1135x over previous
#include <cuda_runtime.h>
#include <cuda_bf16.h>
#include <cuda_fp16.h>
#include <cstdint>

#define BB 4
#define NN 2048
#define CC 320
#define HH 5
#define DD 64
#define GG (BB*HH)      // 20
#define ROWS (BB*NN)    // 8192

// scratch (allocation-free rule: __device__ globals)
__device__ __nv_bfloat16 g_xh[ROWS*CC];    // x split hi
__device__ __nv_bfloat16 g_xl[ROWS*CC];    // x split lo
__device__ __nv_bfloat16 g_wth[3*CC*CC];   // W^T split hi: [ot][n][k]
__device__ __nv_bfloat16 g_wtl[3*CC*CC];   // W^T split lo
__device__ __half        g_qf[GG*NN*DD];   // folded 0.125*e_i, fp16 single
__device__ __half        g_kf[GG*NN*DD];   // folded e_j, fp16 single
__device__ __half        g_vf[GG*DD*NN];   // transposed (g,d,n), fp16 single
__device__ __nv_bfloat16 g_oh[ROWS*CC];    // attn out, merged (b*N+n, h*64+d), hi
__device__ __nv_bfloat16 g_ol[ROWS*CC];    // lo

// ============================ helpers ======================================
__device__ __forceinline__ void mma_bf16(float* d,
    uint32_t a0, uint32_t a1, uint32_t a2, uint32_t a3,
    uint32_t b0, uint32_t b1)
{
    asm volatile(
        "mma.sync.aligned.m16n8k16.row.col.f32.bf16.bf16.f32 "
        "{%0,%1,%2,%3}, {%4,%5,%6,%7}, {%8,%9}, {%0,%1,%2,%3};"
        : "+f"(d[0]), "+f"(d[1]), "+f"(d[2]), "+f"(d[3])
        : "r"(a0), "r"(a1), "r"(a2), "r"(a3), "r"(b0), "r"(b1));
}

__device__ __forceinline__ void mma_fp16(float* d,
    uint32_t a0, uint32_t a1, uint32_t a2, uint32_t a3,
    uint32_t b0, uint32_t b1)
{
    asm volatile(
        "mma.sync.aligned.m16n8k16.row.col.f32.f16.f16.f32 "
        "{%0,%1,%2,%3}, {%4,%5,%6,%7}, {%8,%9}, {%0,%1,%2,%3};"
        : "+f"(d[0]), "+f"(d[1]), "+f"(d[2]), "+f"(d[3])
        : "r"(a0), "r"(a1), "r"(a2), "r"(a3), "r"(b0), "r"(b1));
}

__device__ __forceinline__ void bf16_split(float v, __nv_bfloat16& h, __nv_bfloat16& l) {
    h = __float2bfloat16(v);
    l = __float2bfloat16(v - __bfloat162float(h));
}

__device__ __forceinline__ uint32_t pack_half2(float a, float b) {
    __half2 t = __floats2half2_rn(a, b);     // x=a (low), y=b (high)
    return *(uint32_t*)&t;
}

__device__ __forceinline__ uint32_t smem_u32(const void* p) {
    uint32_t a;
    asm("{ .reg .u64 t; cvta.to.shared.u64 t, %1; cvt.u32.u64 %0, t; }"
        : "=r"(a) : "l"(p));
    return a;
}

__device__ __forceinline__ void cp16(uint32_t dst, const void* src) {
    asm volatile("cp.async.cg.shared.global [%0], [%1], 16;"
                 :: "r"(dst), "l"(src) : "memory");
}
#define CP_COMMIT() asm volatile("cp.async.commit_group;" ::: "memory")
#define CP_WAIT0()  asm volatile("cp.async.wait_group 0;" ::: "memory")
#define CP_WAIT1()  asm volatile("cp.async.wait_group 1;" ::: "memory")

// ---------------------------------------------------------------------------
// Prepass A: split x (fp32) into bf16 hi/lo arrays. 2.6M elems, streaming.
// ---------------------------------------------------------------------------
__global__ void __launch_bounds__(256)
split_x_kernel(const float* __restrict__ x)
{
    size_t idx = ((size_t)blockIdx.x*256 + threadIdx.x)*4;
    float4 v = *(const float4*)&x[idx];
    __nv_bfloat16 h0,l0,h1,l1,h2,l2,h3,l3;
    bf16_split(v.x,h0,l0); bf16_split(v.y,h1,l1);
    bf16_split(v.z,h2,l2); bf16_split(v.w,h3,l3);
    __nv_bfloat162 t;
    t.x=h0; t.y=h1; *(__nv_bfloat162*)&g_xh[idx]   = t;
    t.x=h2; t.y=h3; *(__nv_bfloat162*)&g_xh[idx+2] = t;
    t.x=l0; t.y=l1; *(__nv_bfloat162*)&g_xl[idx]   = t;
    t.x=l2; t.y=l3; *(__nv_bfloat162*)&g_xl[idx+2] = t;
}

// ---------------------------------------------------------------------------
// Prepass B: transpose + split Wq/Wk/Wv into g_wth/g_wtl [ot][n][k].
// 32x32 smem tile transpose; both gmem sides coalesced.
// ---------------------------------------------------------------------------
__global__ void __launch_bounds__(256)
split_w_kernel(const float* __restrict__ Wq,
               const float* __restrict__ Wk,
               const float* __restrict__ Wv)
{
    __shared__ float T[32][33];
    const int ot = blockIdx.z;
    const float* __restrict__ W = (ot == 0) ? Wq : (ot == 1) ? Wk : Wv;
    const int k0 = blockIdx.x * 32;
    const int n0 = blockIdx.y * 32;
    const int tx = threadIdx.x & 31;
    const int ty = threadIdx.x >> 5;     // 0..7

    #pragma unroll
    for (int j = 0; j < 4; j++) {
        int k = k0 + ty + 8*j;
        T[ty + 8*j][tx] = W[k*CC + n0 + tx];
    }
    __syncthreads();
    #pragma unroll
    for (int j = 0; j < 4; j++) {
        int n = n0 + ty + 8*j;
        float v = T[tx][ty + 8*j];
        __nv_bfloat16 hh, ll; bf16_split(v, hh, ll);
        size_t o = ((size_t)ot*CC + n)*CC + k0 + tx;
        g_wth[o] = hh;
        g_wtl[o] = ll;
    }
}

// ---------------------------------------------------------------------------
// Kernel 1: QKV projection, bf16 hi/lo 3-chain MMA.
// Inputs pre-split -> loop is pure double-buffered cp.async + MMA (no splits).
// V epilogue transposes in smem and writes g_vf (g,d,n) fp16 directly.
// ---------------------------------------------------------------------------
#define X_STRIDE_W 20      // words per row (40 halves: 32 data + 8 pad)
#define TS_STRIDE_H 136    // transpose buffer row stride in halves (272 B)
// per-stage byte offsets within smq (stage stride 30720 B):
//  XH +0 (10240), XL +10240, WH +20480 (5120), WL +25600
__global__ void __launch_bounds__(256)
qkv_mma_kernel(const float* __restrict__ edge)
{
    __shared__ uint32_t smq[15360];          // 61440 B (2 stages)
    const uint32_t sb = smem_u32(smq);

    const int tid  = threadIdx.x;
    const int wid  = tid >> 5;
    const int lane = tid & 31;
    const int lq   = lane >> 2;
    const int cq   = lane & 3;
    const int rb   = wid * 16;
    const int colt = blockIdx.x;       // 0..14
    const int ot   = colt / 5;         // 0=q 1=k 2=v
    const int h    = colt % 5;
    const int wc0  = h * 64;
    const int row0 = blockIdx.y * 128;

    const __nv_bfloat16* __restrict__ wh = g_wth + (size_t)ot*CC*CC;
    const __nv_bfloat16* __restrict__ wl = g_wtl + (size_t)ot*CC*CC;

    // prefetch stage 0 (k0 = 0)
    {
        #pragma unroll
        for (int i = 0; i < 2; i++) {            // X hi/lo: 512 chunks each
            int c = tid + 256*i;
            int r = c >> 2, ch = c & 3;
            cp16(sb + 0     + r*80 + ch*16, g_xh + (size_t)(row0 + r)*CC + ch*8);
            cp16(sb + 10240 + r*80 + ch*16, g_xl + (size_t)(row0 + r)*CC + ch*8);
        }
        {                                         // W hi/lo: 256 chunks each
            int n = tid >> 2, ch = tid & 3;
            cp16(sb + 20480 + n*80 + ch*16, wh + (size_t)(wc0 + n)*CC + ch*8);
            cp16(sb + 25600 + n*80 + ch*16, wl + (size_t)(wc0 + n)*CC + ch*8);
        }
        CP_COMMIT();
    }

    float acc[8][4] = {};

    for (int it = 0; it < 10; it++) {
        const uint32_t cur = (it & 1) ? 30720u : 0u;

        if (it + 1 < 10) {
            const int k0n = (it + 1) * 32;
            const uint32_t nxt = (it & 1) ? 0u : 30720u;
            #pragma unroll
            for (int i = 0; i < 2; i++) {
                int c = tid + 256*i;
                int r = c >> 2, ch = c & 3;
                cp16(sb + nxt + 0     + r*80 + ch*16,
                     g_xh + (size_t)(row0 + r)*CC + k0n + ch*8);
                cp16(sb + nxt + 10240 + r*80 + ch*16,
                     g_xl + (size_t)(row0 + r)*CC + k0n + ch*8);
            }
            {
                int n = tid >> 2, ch = tid & 3;
                cp16(sb + nxt + 20480 + n*80 + ch*16,
                     wh + (size_t)(wc0 + n)*CC + k0n + ch*8);
                cp16(sb + nxt + 25600 + n*80 + ch*16,
                     wl + (size_t)(wc0 + n)*CC + k0n + ch*8);
            }
            CP_COMMIT();
            CP_WAIT1();
        } else {
            CP_WAIT0();
        }
        __syncthreads();            // current stage ready; prior MMA done

        const uint32_t* XhW = (const uint32_t*)((const char*)smq + cur);
        const uint32_t* XlW = (const uint32_t*)((const char*)smq + cur + 10240);
        const uint32_t* WhW = (const uint32_t*)((const char*)smq + cur + 20480);
        const uint32_t* WlW = (const uint32_t*)((const char*)smq + cur + 25600);

        #pragma unroll
        for (int kc = 0; kc < 2; kc++) {
            const int wi = kc*8 + cq;
            uint32_t ah0 = XhW[(rb + lq    )*X_STRIDE_W + wi];
            uint32_t ah1 = XhW[(rb + lq + 8)*X_STRIDE_W + wi];
            uint32_t ah2 = XhW[(rb + lq    )*X_STRIDE_W + wi + 4];
            uint32_t ah3 = XhW[(rb + lq + 8)*X_STRIDE_W + wi + 4];
            uint32_t al0 = XlW[(rb + lq    )*X_STRIDE_W + wi];
            uint32_t al1 = XlW[(rb + lq + 8)*X_STRIDE_W + wi];
            uint32_t al2 = XlW[(rb + lq    )*X_STRIDE_W + wi + 4];
            uint32_t al3 = XlW[(rb + lq + 8)*X_STRIDE_W + wi + 4];
            #pragma unroll
            for (int nb = 0; nb < 8; nb++) {
                uint32_t bh0 = WhW[(nb*8 + lq)*X_STRIDE_W + wi];
                uint32_t bh1 = WhW[(nb*8 + lq)*X_STRIDE_W + wi + 4];
                uint32_t bl0 = WlW[(nb*8 + lq)*X_STRIDE_W + wi];
                uint32_t bl1 = WlW[(nb*8 + lq)*X_STRIDE_W + wi + 4];
                mma_bf16(acc[nb], ah0, ah1, ah2, ah3, bh0, bh1);
                mma_bf16(acc[nb], ah0, ah1, ah2, ah3, bl0, bl1);
                mma_bf16(acc[nb], al0, al1, al2, al3, bh0, bh1);
            }
        }
        __syncthreads();            // all warps done before this buf is refilled
    }

    // ---- epilogue ----
    const int r0 = row0 + rb + lq;
    const int b  = r0 >> 11;
    const int n0 = r0 & 2047;
    const int n1 = n0 + 8;
    const int g  = b*HH + h;

    if (ot == 2) {
        // V: transpose via smem (reuse tile area) and write g_vf (g,d,n) fp16.
        __half* Ts = (__half*)smq;             // 64 x 136 halves = 17408 B
        const int nl = rb + lq;                // local n within tile (0..127)
        #pragma unroll
        for (int nb = 0; nb < 8; nb++) {
            int col = nb*8 + 2*cq;             // d index
            Ts[ col     *TS_STRIDE_H + nl    ] = __float2half_rn(acc[nb][0]);
            Ts[(col + 1)*TS_STRIDE_H + nl    ] = __float2half_rn(acc[nb][1]);
            Ts[ col     *TS_STRIDE_H + nl + 8] = __float2half_rn(acc[nb][2]);
            Ts[(col + 1)*TS_STRIDE_H + nl + 8] = __float2half_rn(acc[nb][3]);
        }
        __syncthreads();
        // cooperative coalesced store: thread -> (d = tid>>2, n-chunk = tid&3)
        const int d  = tid >> 2;
        const int ch = tid & 3;
        const int n0t = row0 & 2047;           // tile base n within one b
        const uint4* src = (const uint4*)&Ts[d*TS_STRIDE_H + ch*32];
        uint4* dst = (uint4*)&g_vf[((size_t)g*DD + d)*NN + n0t + ch*32];
        #pragma unroll
        for (int i = 0; i < 4; i++) dst[i] = src[i];
    } else {
        const size_t base0 = ((size_t)g*NN + n0)*DD;
        const size_t base1 = ((size_t)g*NN + n1)*DD;
        const int eb = g & 3;                        // g % B  (batch-minor!)
        const float s  = (ot == 0) ? 0.125f : 1.0f;
        const float f0 = edge[eb*NN + n0] * s;
        const float f1 = edge[eb*NN + n1] * s;
        __half* __restrict__ df = (ot == 0) ? g_qf : g_kf;
        #pragma unroll
        for (int nb = 0; nb < 8; nb++) {
            int col = nb*8 + 2*cq;
            __half2 t0 = __floats2half2_rn(acc[nb][0]*f0, acc[nb][1]*f0);
            __half2 t1 = __floats2half2_rn(acc[nb][2]*f1, acc[nb][3]*f1);
            *(__half2*)&df[base0 + col] = t0;
            *(__half2*)&df[base1 + col] = t1;
        }
    }
}

// ---------------------------------------------------------------------------
// Kernel 2: flash attention, fp16 single-chain S and PV (verified R14/R16).
// ---------------------------------------------------------------------------
#define QK_STRIDE_W 36          // words per row (144 B: 128 data + 16 pad)
#define V_STRIDE_W  68          // words per row (272 B: 256 data + 16 pad)
#define Q_B   0
#define K0_B  18432
#define K1_B  36864
#define V0_B  55296
#define V1_B  72704
#define ATTN_SMEM 90112

__global__ void __launch_bounds__(256, 2)
attn_mma_kernel()
{
    extern __shared__ char smx[];
    const uint32_t sb = smem_u32(smx);
    uint32_t* QW = (uint32_t*)(smx + Q_B);

    const int tid  = threadIdx.x;
    const int w    = tid >> 5;
    const int lane = tid & 31;
    const int lq   = lane >> 2;
    const int cq   = lane & 3;
    const int g    = blockIdx.y;
    const int i0   = blockIdx.x * 128;
    const int rb   = w * 16;

    // ---- prologue: Q tile (group 0) ----
    #pragma unroll
    for (int i = 0; i < 4; i++) {
        int c = tid + 256*i;                 // 1024 chunks
        int r = c >> 3, cc = c & 7;
        cp16(sb + Q_B + r*144 + cc*16, g_qf + ((size_t)g*NN + i0 + r)*DD + cc*8);
    }
    CP_COMMIT();

    // ---- prologue: K/V stage 0 (group 1) ----
    #pragma unroll
    for (int i = 0; i < 4; i++) {
        int c = tid + 256*i;
        int j = c >> 3, cc = c & 7;
        cp16(sb + K0_B + j*144 + cc*16, g_kf + ((size_t)g*NN + j)*DD + cc*8);
    }
    #pragma unroll
    for (int i = 0; i < 4; i++) {
        int c = tid + 256*i;
        int d = c >> 4, cc = c & 15;
        cp16(sb + V0_B + d*272 + cc*16, g_vf + ((size_t)g*DD + d)*NN + cc*8);
    }
    CP_COMMIT();

    float Oacc[8][4] = {};
    float lsum0 = 0.0f, lsum1 = 0.0f;

    for (int jt = 0; jt < 16; jt++) {
        const int buf = jt & 1;

        // ---- prefetch next stage ----
        if (jt + 1 < 16) {
            const int j0n = (jt + 1) * 128;
            const uint32_t kb = (buf ? K0_B : K1_B);
            const uint32_t vb = (buf ? V0_B : V1_B);
            #pragma unroll
            for (int i = 0; i < 4; i++) {
                int c = tid + 256*i;
                int j = c >> 3, cc = c & 7;
                cp16(sb + kb + j*144 + cc*16,
                     g_kf + ((size_t)g*NN + j0n + j)*DD + cc*8);
            }
            #pragma unroll
            for (int i = 0; i < 4; i++) {
                int c = tid + 256*i;
                int d = c >> 4, cc = c & 15;
                cp16(sb + vb + d*272 + cc*16,
                     g_vf + ((size_t)g*DD + d)*NN + j0n + cc*8);
            }
            CP_COMMIT();
            CP_WAIT1();     // current stage complete; prefetch may be pending
        } else {
            CP_WAIT0();
        }
        __syncthreads();

        uint32_t* KW = (uint32_t*)(smx + (buf ? K1_B : K0_B));
        uint32_t* VW = (uint32_t*)(smx + (buf ? V1_B : V0_B));

        // ---- S = Q K^T : single-chain fp16 ----
        float S[16][4];
        #pragma unroll
        for (int nb = 0; nb < 16; nb++)
            #pragma unroll
            for (int i = 0; i < 4; i++) S[nb][i] = 0.0f;

        #pragma unroll
        for (int kc = 0; kc < 4; kc++) {
            const int wi = kc*8 + cq;
            uint32_t a0 = QW[(rb + lq    )*QK_STRIDE_W + wi];
            uint32_t a1 = QW[(rb + lq + 8)*QK_STRIDE_W + wi];
            uint32_t a2 = QW[(rb + lq    )*QK_STRIDE_W + wi + 4];
            uint32_t a3 = QW[(rb + lq + 8)*QK_STRIDE_W + wi + 4];
            #pragma unroll
            for (int nb = 0; nb < 16; nb++) {
                uint32_t b0 = KW[(nb*8 + lq)*QK_STRIDE_W + wi];
                uint32_t b1 = KW[(nb*8 + lq)*QK_STRIDE_W + wi + 4];
                mma_fp16(S[nb], a0, a1, a2, a3, b0, b1);
            }
        }

        // ---- softmax (logits bounded, no max needed) ----
        #pragma unroll
        for (int nb = 0; nb < 16; nb++) {
            float p0 = __expf(S[nb][0]);
            float p1 = __expf(S[nb][1]);
            float p2 = __expf(S[nb][2]);
            float p3 = __expf(S[nb][3]);
            S[nb][0] = p0; S[nb][1] = p1; S[nb][2] = p2; S[nb][3] = p3;
            lsum0 += p0 + p1;
            lsum1 += p2 + p3;
        }

        // ---- O += P V : single-chain fp16 P, fp16 V ----
        #pragma unroll
        for (int kc = 0; kc < 8; kc++) {
            uint32_t a0 = pack_half2(S[2*kc][0],   S[2*kc][1]);
            uint32_t a1 = pack_half2(S[2*kc][2],   S[2*kc][3]);
            uint32_t a2 = pack_half2(S[2*kc+1][0], S[2*kc+1][1]);
            uint32_t a3 = pack_half2(S[2*kc+1][2], S[2*kc+1][3]);
            const int wi = kc*8 + cq;
            #pragma unroll
            for (int nd = 0; nd < 8; nd++) {
                uint32_t b0 = VW[(nd*8 + lq)*V_STRIDE_W + wi];
                uint32_t b1 = VW[(nd*8 + lq)*V_STRIDE_W + wi + 4];
                mma_fp16(Oacc[nd], a0, a1, a2, a3, b0, b1);
            }
        }
        __syncthreads();   // all warps done with this stage before it is refilled
    }

    // ---- reduce row sums across the quad sharing each row ----
    lsum0 += __shfl_xor_sync(0xFFFFFFFF, lsum0, 1);
    lsum0 += __shfl_xor_sync(0xFFFFFFFF, lsum0, 2);
    lsum1 += __shfl_xor_sync(0xFFFFFFFF, lsum1, 1);
    lsum1 += __shfl_xor_sync(0xFFFFFFFF, lsum1, 2);
    const float inv0 = 1.0f / lsum0;
    const float inv1 = 1.0f / lsum1;

    // ---- write O as bf16 hi/lo into merged layout (row, h*64+d) ----
    const int b = g / HH, h = g % HH;
    const int rowg0 = b*NN + i0 + rb + lq;
    const int rowg1 = rowg0 + 8;
    #pragma unroll
    for (int nd = 0; nd < 8; nd++) {
        int col = h*64 + nd*8 + 2*cq;
        float v00 = Oacc[nd][0]*inv0, v01 = Oacc[nd][1]*inv0;
        float v10 = Oacc[nd][2]*inv1, v11 = Oacc[nd][3]*inv1;
        __nv_bfloat16 h00, l00, h01, l01, h10, l10, h11, l11;
        bf16_split(v00, h00, l00); bf16_split(v01, h01, l01);
        bf16_split(v10, h10, l10); bf16_split(v11, h11, l11);
        __nv_bfloat162 t;
        t.x = h00; t.y = h01; *(__nv_bfloat162*)&g_oh[(size_t)rowg0*CC + col] = t;
        t.x = l00; t.y = l01; *(__nv_bfloat162*)&g_ol[(size_t)rowg0*CC + col] = t;
        t.x = h10; t.y = h11; *(__nv_bfloat162*)&g_oh[(size_t)rowg1*CC + col] = t;
        t.x = l10; t.y = l11; *(__nv_bfloat162*)&g_ol[(size_t)rowg1*CC + col] = t;
    }
}

// ---------------------------------------------------------------------------
// Kernel 3: output projection, bf16 hi/lo 3-chain MMA + bias (verified R16).
// ---------------------------------------------------------------------------
__global__ void __launch_bounds__(256)
oproj_mma_kernel(const float* __restrict__ Wo,
                 const float* __restrict__ bo,
                 float* __restrict__ out)
{
    __shared__ uint32_t osm[16896];
    const uint32_t sb = smem_u32(osm);
    uint32_t* WhW = osm + 10240;
    uint32_t* WlW = osm + 11520;
    __nv_bfloat16* Wh = (__nv_bfloat16*)WhW;
    __nv_bfloat16* Wl = (__nv_bfloat16*)WlW;

    const int tid  = threadIdx.x;
    const int wid  = tid >> 5;
    const int lane = tid & 31;
    const int lq   = lane >> 2;
    const int cq   = lane & 3;
    const int rb   = wid * 16;
    const int c0   = blockIdx.x * 64;
    const int row0 = blockIdx.y * 128;

    // prologue: prefetch k0=0 into buffer 0
    {
        #pragma unroll
        for (int i = 0; i < 2; i++) {
            int c = tid + 256*i;
            int r = c >> 2, cc = c & 3;
            cp16(sb + (0    )*4 + r*80 + cc*16,
                 g_oh + (size_t)(row0 + r)*CC + cc*8);
            cp16(sb + (2560 )*4 + r*80 + cc*16,
                 g_ol + (size_t)(row0 + r)*CC + cc*8);
        }
        #pragma unroll
        for (int i = 0; i < 2; i++) {
            int c = tid + 256*i;
            int kk = c >> 4, ch = c & 15;
            cp16(sb + (12800)*4 + (uint32_t)(kk*64 + ch*4)*4,
                 &Wo[kk*CC + c0 + ch*4]);
        }
        CP_COMMIT();
    }

    float acc[8][4] = {};

    for (int it = 0; it < 10; it++) {
        const int buf = it & 1;
        const uint32_t xh_off = buf ? 5120u : 0u;
        const uint32_t xl_off = xh_off + 2560u;
        const uint32_t ws_off = buf ? 14848u : 12800u;

        CP_WAIT0();
        __syncthreads();               // current stage ready; prior MMA done

        // split Wo staging -> bf16 hi/lo [n][kk]
        {
            const float* Wst = (const float*)(osm + ws_off);
            #pragma unroll
            for (int i = 0; i < 8; i++) {
                int e = tid + 256*i;
                int n = e & 63, kk = e >> 6;
                float v = Wst[kk*64 + n];
                __nv_bfloat16 hh, ll; bf16_split(v, hh, ll);
                Wh[n*40 + kk] = hh;
                Wl[n*40 + kk] = ll;
            }
        }

        // prefetch next stage into alternate buffers (overlaps MMA)
        if (it + 1 < 10) {
            const int k0n = (it + 1) * 32;
            const uint32_t xh_n = buf ? 0u : 5120u;
            const uint32_t xl_n = xh_n + 2560u;
            const uint32_t ws_n = buf ? 12800u : 14848u;
            #pragma unroll
            for (int i = 0; i < 2; i++) {
                int c = tid + 256*i;
                int r = c >> 2, cc = c & 3;
                cp16(sb + xh_n*4 + r*80 + cc*16,
                     g_oh + (size_t)(row0 + r)*CC + k0n + cc*8);
                cp16(sb + xl_n*4 + r*80 + cc*16,
                     g_ol + (size_t)(row0 + r)*CC + k0n + cc*8);
            }
            #pragma unroll
            for (int i = 0; i < 2; i++) {
                int c = tid + 256*i;
                int kk = c >> 4, ch = c & 15;
                cp16(sb + ws_n*4 + (uint32_t)(kk*64 + ch*4)*4,
                     &Wo[(k0n + kk)*CC + c0 + ch*4]);
            }
            CP_COMMIT();
        }
        __syncthreads();               // Wh/Wl ready for all warps

        const uint32_t* XhW = osm + xh_off;
        const uint32_t* XlW = osm + xl_off;
        #pragma unroll
        for (int kc = 0; kc < 2; kc++) {
            const int wi = kc*8 + cq;
            uint32_t ah0 = XhW[(rb + lq    )*X_STRIDE_W + wi];
            uint32_t ah1 = XhW[(rb + lq + 8)*X_STRIDE_W + wi];
            uint32_t ah2 = XhW[(rb + lq    )*X_STRIDE_W + wi + 4];
            uint32_t ah3 = XhW[(rb + lq + 8)*X_STRIDE_W + wi + 4];
            uint32_t al0 = XlW[(rb + lq    )*X_STRIDE_W + wi];
            uint32_t al1 = XlW[(rb + lq + 8)*X_STRIDE_W + wi];
            uint32_t al2 = XlW[(rb + lq    )*X_STRIDE_W + wi + 4];
            uint32_t al3 = XlW[(rb + lq + 8)*X_STRIDE_W + wi + 4];
            #pragma unroll
            for (int nb = 0; nb < 8; nb++) {
                uint32_t bh0 = WhW[(nb*8 + lq)*X_STRIDE_W + wi];
                uint32_t bh1 = WhW[(nb*8 + lq)*X_STRIDE_W + wi + 4];
                uint32_t bl0 = WlW[(nb*8 + lq)*X_STRIDE_W + wi];
                uint32_t bl1 = WlW[(nb*8 + lq)*X_STRIDE_W + wi + 4];
                mma_bf16(acc[nb], ah0, ah1, ah2, ah3, bh0, bh1);
                mma_bf16(acc[nb], ah0, ah1, ah2, ah3, bl0, bl1);
                mma_bf16(acc[nb], al0, al1, al2, al3, bh0, bh1);
            }
        }
    }

    // ---- epilogue: add bias, write fp32 out ----
    const int r0 = row0 + rb + lq;
    const int r1 = r0 + 8;
    #pragma unroll
    for (int nb = 0; nb < 8; nb++) {
        int col = c0 + nb*8 + 2*cq;
        float b0v = bo[col], b1v = bo[col+1];
        *(float2*)&out[(size_t)r0*CC + col] =
            make_float2(acc[nb][0] + b0v, acc[nb][1] + b1v);
        *(float2*)&out[(size_t)r1*CC + col] =
            make_float2(acc[nb][2] + b0v, acc[nb][3] + b1v);
    }
}

// ---------------------------------------------------------------------------
extern "C" void kernel_launch(void* const* d_in, const int* in_sizes, int n_in,
                              void* d_out, int out_size)
{
    const float* x    = (const float*)d_in[0];
    const float* edge = (const float*)d_in[1];
    const float* Wq   = (const float*)d_in[2];
    const float* Wk   = (const float*)d_in[3];
    const float* Wv   = (const float*)d_in[4];
    const float* Wo   = (const float*)d_in[5];
    const float* bo   = (const float*)d_in[6];
    float* out = (float*)d_out;

    split_x_kernel<<<ROWS*CC/(256*4), 256>>>(x);
    split_w_kernel<<<dim3(10, 10, 3), 256>>>(Wq, Wk, Wv);

    qkv_mma_kernel<<<dim3(15, 64), 256>>>(edge);

    cudaFuncSetAttribute(attn_mma_kernel,
                         cudaFuncAttributeMaxDynamicSharedMemorySize, ATTN_SMEM);
    attn_mma_kernel<<<dim3(16, GG), 256, ATTN_SMEM>>>();

    oproj_mma_kernel<<<dim3(5, 64), 256>>>(Wo, bo, out);
}